// round 14
// baseline (speedup 1.0000x reference)
#include <cuda_runtime.h>
#include <cuda_fp16.h>
#include <stdint.h>
#include <math.h>

#define NTHREADS 256
#define NCTAS 2048
#define BTV (4096 * 64 * 96)

#define O_XS 0
#define O_AA 34816
#define O_B 51200
#define O_Q 59392
#define O_K 75776
#define O_V 92160
#define O_SRED 108544
#define SMEM_BYTES 110592

#define SW(r, inner) ((r) * 128 + ((inner) ^ (((r) & 7) << 4)))

__device__ __align__(16) __half g_wqkv[49152];  // [(l*3+m)][n][k] -> l: [192][64]
__device__ __align__(16) __half g_wo[16384];
__device__ __align__(16) __half g_w1[65536];
__device__ __align__(16) __half g_w2[65536];
__device__ __align__(16) __half g_lmh[6144];
__device__ __align__(16) __half g_lml[6144];
__device__ float g_partial[NCTAS];

__device__ __forceinline__ uint32_t smem_u32(const void* p) {
  uint32_t a;
  asm("{ .reg .u64 t; cvta.to.shared.u64 t, %1; cvt.u32.u64 %0, t; }"
      : "=r"(a) : "l"(p));
  return a;
}
__device__ __forceinline__ uint32_t f2h2(float x, float y) {
  __half2 h = __floats2half2_rn(x, y);
  return *(uint32_t*)&h;
}

__device__ __forceinline__ void stageB(const __half* __restrict__ g, char* s,
                                       int tid) {
  const uint4* src = (const uint4*)g;
  for (int i = tid; i < 512; i += NTHREADS) {
    int n = i >> 3, u = (i & 7) * 16;
    *(uint4*)(s + SW(n, u)) = src[i];
  }
}
// 128-row stage (wq+wk fused tile)
__device__ __forceinline__ void stageB128(const __half* __restrict__ g,
                                          char* s, int tid) {
  const uint4* src = (const uint4*)g;
  for (int i = tid; i < 1024; i += NTHREADS) {
    int n = i >> 3, u = (i & 7) * 16;
    *(uint4*)(s + SW(n, u)) = src[i];
  }
}
__device__ __forceinline__ void stageB96(const __half* __restrict__ g, char* s,
                                         int tid) {
  const uint4* src = (const uint4*)g;
  for (int i = tid; i < 768; i += NTHREADS) {
    int n = i >> 3, u = (i & 7) * 16;
    *(uint4*)(s + SW(n, u)) = src[i];
  }
}

#define LDSM_X4(a0, a1, a2, a3, addr)                                        \
  asm volatile("ldmatrix.sync.aligned.m8n8.x4.shared.b16 {%0,%1,%2,%3}, [%4];" \
               : "=r"(a0), "=r"(a1), "=r"(a2), "=r"(a3) : "r"(addr))
#define LDSM_X2(b0, b1, addr)                                                \
  asm volatile("ldmatrix.sync.aligned.m8n8.x2.shared.b16 {%0,%1}, [%2];"     \
               : "=r"(b0), "=r"(b1) : "r"(addr))
#define LDSM_X4T(a0, a1, a2, a3, addr)                                       \
  asm volatile(                                                              \
      "ldmatrix.sync.aligned.m8n8.x4.trans.shared.b16 {%0,%1,%2,%3}, [%4];"  \
      : "=r"(a0), "=r"(a1), "=r"(a2), "=r"(a3) : "r"(addr))
#define MMA16816(c, a0, a1, a2, a3, b0, b1)                                  \
  asm volatile(                                                              \
      "mma.sync.aligned.m16n8k16.row.col.f32.f16.f16.f32 "                   \
      "{%0,%1,%2,%3}, {%4,%5,%6,%7}, {%8,%9}, {%0,%1,%2,%3};"                \
      : "+f"((c)[0]), "+f"((c)[1]), "+f"((c)[2]), "+f"((c)[3])               \
      : "r"(a0), "r"(a1), "r"(a2), "r"(a3), "r"(b0), "r"(b1))

// 128xNx64 GEMM core, NTILES n-tiles of 8 (x2 B loads — proven fastest)
template <int NTILES>
__device__ __forceinline__ void gemm_n(uint32_t a_addr, uint32_t b_addr,
                                       int w, int lane,
                                       float acc[NTILES][4]) {
#pragma unroll
  for (int nt = 0; nt < NTILES; nt++)
#pragma unroll
    for (int e = 0; e < 4; e++) acc[nt][e] = 0.f;
  const int l15 = lane & 15;
  const int ahi = (lane >> 4) << 4;
  const int rowA = w * 16 + l15;
  const uint32_t a_base = a_addr + rowA * 128;
  const int aswz = (rowA & 7) << 4;
  const int bl = lane & 7;
  const int bhi = (lane & 8) << 1;
#pragma unroll
  for (int kt = 0; kt < 4; kt++) {
    uint32_t a0, a1, a2, a3;
    LDSM_X4(a0, a1, a2, a3, a_base + ((kt * 32 + ahi) ^ aswz));
#pragma unroll
    for (int nt = 0; nt < NTILES; nt++) {
      uint32_t b0, b1;
      LDSM_X2(b0, b1, b_addr + SW(nt * 8 + bl, kt * 32 + bhi));
      MMA16816(acc[nt], a0, a1, a2, a3, b0, b1);
    }
  }
}

// LayerNorm of xs row -> v[64] (R11 form, 128 threads)
__device__ __forceinline__ void ln_row(const float* row, float* v,
                                       const float* __restrict__ g,
                                       const float* __restrict__ b) {
  float s = 0.f, ss = 0.f;
#pragma unroll
  for (int i = 0; i < 16; i++) {
    float4 a = *(const float4*)(row + i * 4);
    v[i * 4] = a.x; v[i * 4 + 1] = a.y; v[i * 4 + 2] = a.z; v[i * 4 + 3] = a.w;
    s += a.x + a.y + a.z + a.w;
    ss += a.x * a.x + a.y * a.y + a.z * a.z + a.w * a.w;
  }
  float mean = s * 0.015625f;
  float inv = rsqrtf(ss * 0.015625f - mean * mean + 1e-5f);
#pragma unroll
  for (int c = 0; c < 64; c++)
    v[c] = (v[c] - mean) * inv * __ldg(g + c) + __ldg(b + c);
}

__device__ __forceinline__ void row_to_A(const float* v, char* aAc, int r) {
#pragma unroll
  for (int q8 = 0; q8 < 8; q8++) {
    uint32_t h[4];
#pragma unroll
    for (int e = 0; e < 4; e++)
      h[e] = f2h2(v[q8 * 8 + e * 2], v[q8 * 8 + e * 2 + 1]);
    *(uint4*)(aAc + SW(r, q8 * 16)) = *(uint4*)h;
  }
}

// ---------------- prep ----------------------------------------------------
__global__ void prep_kernel(const float* __restrict__ wq,
                            const float* __restrict__ wk,
                            const float* __restrict__ wv,
                            const float* __restrict__ wo,
                            const float* __restrict__ w1,
                            const float* __restrict__ w2,
                            const float* __restrict__ lm_w) {
  int i = blockIdx.x * blockDim.x + threadIdx.x;
  if (i < 49152) {
    int l = i / 12288, rr = i % 12288;
    int m = rr / 4096, r2 = rr % 4096;
    int n = r2 >> 6, k = r2 & 63;
    int h = n >> 4, s = n & 15;
    const float* src = (m == 0) ? wq : (m == 1) ? wk : wv;
    g_wqkv[i] = __float2half(src[l * 4096 + h * 1024 + k * 16 + s]);
  } else if (i < 65536) {
    int j = i - 49152;
    int l = j >> 12, n = (j >> 6) & 63, k = j & 63;
    g_wo[j] = __float2half(wo[l * 4096 + k * 64 + n]);
  } else if (i < 131072) {
    int j = i - 65536;
    int lj = j >> 12, n = (j >> 6) & 63, k = j & 63;
    int l = lj >> 2, jj = lj & 3;
    g_w1[j] = __float2half(w1[l * 16384 + k * 256 + jj * 64 + n]);
  } else if (i < 196608) {
    int j = i - 131072;
    int lj = j >> 12, n = (j >> 6) & 63, k = j & 63;
    int l = lj >> 2, jj = lj & 3;
    g_w2[j] = __float2half(w2[l * 16384 + (jj * 64 + k) * 64 + n]);
  } else if (i < 202752) {
    int j = i - 196608;
    int n = j >> 6, k = j & 63;
    float v = lm_w[k * 96 + n];
    __half hi = __float2half(v);
    g_lmh[j] = hi;
    g_lml[j] = __float2half(v - __half2float(hi));
  }
}

// ---------------- main fused kernel: 1 CTA = 2 sequences ------------------
__global__ void __launch_bounds__(NTHREADS, 2) slm_kernel(
    const int* __restrict__ idx, const int* __restrict__ targets,
    const float* __restrict__ tok_emb, const float* __restrict__ pos_emb,
    const float* __restrict__ ln1_g, const float* __restrict__ ln1_b,
    const float* __restrict__ bo, const float* __restrict__ ln2_g,
    const float* __restrict__ ln2_b, const float* __restrict__ b1,
    const float* __restrict__ b2, const float* __restrict__ lnf_g,
    const float* __restrict__ lnf_b, const float* __restrict__ lm_b,
    float* __restrict__ out, int write_logits) {
  extern __shared__ char sm[];
  float* xs = (float*)(sm + O_XS);
  char* aAc = sm + O_AA;
  char* Bsc = sm + O_B;
  float* sred = (float*)(sm + O_SRED);
  const int b = blockIdx.x;
  const int tid = threadIdx.x;
  const int w = tid >> 5, lane = tid & 31;
  const int g = lane >> 2, tg = lane & 3;
  const int r0 = w * 16 + g;
  const uint32_t smb = smem_u32(sm);
  const uint32_t a_aA = smb + O_AA, a_B = smb + O_B;
  const uint32_t a_q = smb + O_Q, a_k = smb + O_K, a_v = smb + O_V;

  for (int i = tid; i < 8192; i += NTHREADS) {
    int r = i >> 6, c = i & 63;
    xs[r * 68 + c] =
        tok_emb[idx[b * 128 + r] * 64 + c] + pos_emb[(r & 63) * 64 + c];
  }
  __syncthreads();

  float acc[8][4];

  for (int l = 0; l < 4; l++) {
    // ---- ln1 -> A; stage [wq;wk] (128 rows) -> O_V, wv -> B ----
    stageB128(g_wqkv + (l * 3) * 4096, sm + O_V, tid);
    stageB(g_wqkv + (l * 3 + 2) * 4096, Bsc, tid);
    if (tid < 128) {
      float v[64];
      ln_row(xs + tid * 68, v, ln1_g + l * 64, ln1_b + l * 64);
      row_to_A(v, aAc, tid);
    }
    __syncthreads();
    // ---- fused Q+K GEMM (N=128, weights in O_V) ----
    {
      float qk[16][4];
      gemm_n<16>(a_aA, a_v, w, lane, qk);
#pragma unroll
      for (int nt = 0; nt < 8; nt++) {
        int col = nt * 8 + tg * 2;
        *(uint32_t*)(sm + O_Q + SW(r0, col * 2)) = f2h2(qk[nt][0], qk[nt][1]);
        *(uint32_t*)(sm + O_Q + SW(r0 + 8, col * 2)) =
            f2h2(qk[nt][2], qk[nt][3]);
        *(uint32_t*)(sm + O_K + SW(r0, col * 2)) =
            f2h2(qk[8 + nt][0], qk[8 + nt][1]);
        *(uint32_t*)(sm + O_K + SW(r0 + 8, col * 2)) =
            f2h2(qk[8 + nt][2], qk[8 + nt][3]);
      }
    }
    // ---- V GEMM compute (weights in B; no barrier needed before compute) --
    gemm_n<8>(a_aA, a_B, w, lane, acc);
    __syncthreads();  // all warps done reading O_V weights; q/k visible
    // ---- V epilogue -> O_V (overwrites weights) ----
#pragma unroll
    for (int nt = 0; nt < 8; nt++) {
      int col = nt * 8 + tg * 2;
      *(uint32_t*)(sm + O_V + SW(r0, col * 2)) = f2h2(acc[nt][0], acc[nt][1]);
      *(uint32_t*)(sm + O_V + SW(r0 + 8, col * 2)) =
          f2h2(acc[nt][2], acc[nt][3]);
    }
    __syncthreads();
    // ---- attention: warp = (seq, head); balanced causal skip ----
    stageB(g_wo + l * 4096, Bsc, tid);
    {
      const int bl = lane & 7;
      const int l15 = lane & 15;
      const int ahi = (lane >> 4) << 4;
      const int bhi = (lane & 8) << 1;
      const int vgrp = lane >> 4;
      const int seq0a = (w >> 2) * 64;
      const int h = w & 3;
      const int hb = h * 32;
#pragma unroll
      for (int mi = 0; mi < 4; mi++) {
        const int rowA = seq0a + mi * 16 + l15;
        uint32_t a0, a1, a2, a3;
        LDSM_X4(a0, a1, a2, a3,
                a_q + rowA * 128 + ((hb + ahi) ^ ((rowA & 7) << 4)));
        const int NT = 2 * (mi + 1);
        float S[8][4];
#pragma unroll
        for (int nt = 0; nt < 8; nt++) {
          if (nt >= NT) break;
#pragma unroll
          for (int e = 0; e < 4; e++) S[nt][e] = 0.f;
          uint32_t b0, b1;
          LDSM_X2(b0, b1, a_k + SW(seq0a + nt * 8 + bl, hb + bhi));
          MMA16816(S[nt], a0, a1, a2, a3, b0, b1);
        }
        const int tlo = mi * 16 + g;
        float mx0 = -1e30f, mx1 = -1e30f;
#pragma unroll
        for (int nt = 0; nt < 8; nt++) {
          if (nt >= NT) break;
          int c0 = nt * 8 + tg * 2;
          S[nt][0] = (c0 <= tlo) ? S[nt][0] * 0.25f : -1e30f;
          S[nt][1] = (c0 + 1 <= tlo) ? S[nt][1] * 0.25f : -1e30f;
          S[nt][2] = (c0 <= tlo + 8) ? S[nt][2] * 0.25f : -1e30f;
          S[nt][3] = (c0 + 1 <= tlo + 8) ? S[nt][3] * 0.25f : -1e30f;
          mx0 = fmaxf(mx0, fmaxf(S[nt][0], S[nt][1]));
          mx1 = fmaxf(mx1, fmaxf(S[nt][2], S[nt][3]));
        }
        mx0 = fmaxf(mx0, __shfl_xor_sync(0xffffffffu, mx0, 1));
        mx0 = fmaxf(mx0, __shfl_xor_sync(0xffffffffu, mx0, 2));
        mx1 = fmaxf(mx1, __shfl_xor_sync(0xffffffffu, mx1, 1));
        mx1 = fmaxf(mx1, __shfl_xor_sync(0xffffffffu, mx1, 2));
        float sum0 = 0.f, sum1 = 0.f;
#pragma unroll
        for (int nt = 0; nt < 8; nt++) {
          if (nt >= NT) break;
          S[nt][0] = __expf(S[nt][0] - mx0);
          S[nt][1] = __expf(S[nt][1] - mx0);
          S[nt][2] = __expf(S[nt][2] - mx1);
          S[nt][3] = __expf(S[nt][3] - mx1);
          sum0 += S[nt][0] + S[nt][1];
          sum1 += S[nt][2] + S[nt][3];
        }
        sum0 += __shfl_xor_sync(0xffffffffu, sum0, 1);
        sum0 += __shfl_xor_sync(0xffffffffu, sum0, 2);
        sum1 += __shfl_xor_sync(0xffffffffu, sum1, 1);
        sum1 += __shfl_xor_sync(0xffffffffu, sum1, 2);
        float ri0 = 1.f / sum0, ri1 = 1.f / sum1;
        float O[2][4];
#pragma unroll
        for (int nt = 0; nt < 2; nt++)
#pragma unroll
          for (int e = 0; e < 4; e++) O[nt][e] = 0.f;
#pragma unroll
        for (int kb = 0; kb < 4; kb++) {
          if (kb > mi) break;
          uint32_t p0 = f2h2(S[2 * kb][0] * ri0, S[2 * kb][1] * ri0);
          uint32_t p1 = f2h2(S[2 * kb][2] * ri1, S[2 * kb][3] * ri1);
          uint32_t p2 = f2h2(S[2 * kb + 1][0] * ri0, S[2 * kb + 1][1] * ri0);
          uint32_t p3 = f2h2(S[2 * kb + 1][2] * ri1, S[2 * kb + 1][3] * ri1);
          int ur = seq0a + kb * 16 + bl + ((lane & 8) ? 8 : 0);
          uint32_t b0, b1, b2, b3;
          LDSM_X4T(b0, b1, b2, b3, a_v + SW(ur, hb + vgrp * 16));
          MMA16816(O[0], p0, p1, p2, p3, b0, b1);
          MMA16816(O[1], p0, p1, p2, p3, b2, b3);
        }
        const int orow = seq0a + mi * 16 + g;
#pragma unroll
        for (int nt = 0; nt < 2; nt++) {
          int col = h * 16 + nt * 8 + tg * 2;
          *(uint32_t*)(aAc + SW(orow, col * 2)) = f2h2(O[nt][0], O[nt][1]);
          *(uint32_t*)(aAc + SW(orow + 8, col * 2)) = f2h2(O[nt][2], O[nt][3]);
        }
      }
    }
    __syncthreads();
    // ---- WO GEMM (wo prestaged): xs += d + bo ----
    gemm_n<8>(a_aA, a_B, w, lane, acc);
    {
      const float* bp = bo + l * 64;
#pragma unroll
      for (int nt = 0; nt < 8; nt++) {
        int col = nt * 8 + tg * 2;
        float bv0 = __ldg(bp + col), bv1 = __ldg(bp + col + 1);
        xs[r0 * 68 + col] += acc[nt][0] + bv0;
        xs[r0 * 68 + col + 1] += acc[nt][1] + bv1;
        xs[(r0 + 8) * 68 + col] += acc[nt][2] + bv0;
        xs[(r0 + 8) * 68 + col + 1] += acc[nt][3] + bv1;
      }
    }
    __syncthreads();
    // ---- ln2 -> A; prestage first MLP chunk ----
    stageB(g_w1 + (l * 4) * 4096, Bsc, tid);
    stageB(g_w2 + (l * 4) * 4096, sm + O_K, tid);
    if (tid < 128) {
      float v[64];
      ln_row(xs + tid * 68, v, ln2_g + l * 64, ln2_b + l * 64);
      row_to_A(v, aAc, tid);
    }
    __syncthreads();
    // ---- MLP: double-buffered w1 (B / O_V), w2 (O_K halves) ----
    char* aMc = sm + O_Q;
    const uint32_t a_aM = a_q;
    for (int j = 0; j < 4; j++) {
      uint32_t a_w1 = (j & 1) ? a_v : a_B;
      uint32_t a_w2 = a_k + ((j & 1) ? 8192 : 0);
      gemm_n<8>(a_aA, a_w1, w, lane, acc);
      {
        const float* bp = b1 + l * 256 + j * 64;
#pragma unroll
        for (int nt = 0; nt < 8; nt++) {
          int col = nt * 8 + tg * 2;
          float bv0 = __ldg(bp + col), bv1 = __ldg(bp + col + 1);
          *(uint32_t*)(aMc + SW(r0, col * 2)) = f2h2(
              fmaxf(acc[nt][0] + bv0, 0.f), fmaxf(acc[nt][1] + bv1, 0.f));
          *(uint32_t*)(aMc + SW(r0 + 8, col * 2)) = f2h2(
              fmaxf(acc[nt][2] + bv0, 0.f), fmaxf(acc[nt][3] + bv1, 0.f));
        }
      }
      if (j < 3)
        stageB(g_w1 + (l * 4 + j + 1) * 4096, (j & 1) ? Bsc : (sm + O_V), tid);
      __syncthreads();
      gemm_n<8>(a_aM, a_w2, w, lane, acc);
      {
        const float* bp = (j == 3) ? (b2 + l * 64) : nullptr;
#pragma unroll
        for (int nt = 0; nt < 8; nt++) {
          int col = nt * 8 + tg * 2;
          float bv0 = bp ? __ldg(bp + col) : 0.f;
          float bv1 = bp ? __ldg(bp + col + 1) : 0.f;
          xs[r0 * 68 + col] += acc[nt][0] + bv0;
          xs[r0 * 68 + col + 1] += acc[nt][1] + bv1;
          xs[(r0 + 8) * 68 + col] += acc[nt][2] + bv0;
          xs[(r0 + 8) * 68 + col + 1] += acc[nt][3] + bv1;
        }
      }
      if (j < 3)
        stageB(g_w2 + (l * 4 + j + 1) * 4096,
               sm + O_K + ((j & 1) ? 0 : 8192), tid);
      __syncthreads();
    }
  }

  // ---- final LN -> split fp16 operands Ah @ O_AA, Al @ O_Q ----
  if (tid < 128) {
    float v[64];
    ln_row(xs + tid * 68, v, lnf_g, lnf_b);
    char* Alc = sm + O_Q;
#pragma unroll
    for (int q8 = 0; q8 < 8; q8++) {
      uint32_t hh[4], hl[4];
#pragma unroll
      for (int e = 0; e < 4; e++) {
        float v0 = v[q8 * 8 + e * 2], v1 = v[q8 * 8 + e * 2 + 1];
        hh[e] = f2h2(v0, v1);
        __half2 hi2 = *(__half2*)&hh[e];
        float2 hif = __half22float2(hi2);
        hl[e] = f2h2(v0 - hif.x, v1 - hif.y);
      }
      *(uint4*)(aAc + SW(tid, q8 * 16)) = *(uint4*)hh;
      *(uint4*)(Alc + SW(tid, q8 * 16)) = *(uint4*)hl;
    }
  }
  stageB96(g_lmh, sm + O_K, tid);
  stageB96(g_lml, sm + O_K + 12288, tid);
  __syncthreads();

  // ---- LM head: 128x96x64 split GEMM ----
  float lacc[12][4];
#pragma unroll
  for (int nt = 0; nt < 12; nt++)
#pragma unroll
    for (int e = 0; e < 4; e++) lacc[nt][e] = 0.f;
  {
    // three accumulate passes: Ah@Bh, Al@Bh, Ah@Bl
    const uint32_t aaddr[3] = {a_aA, a_q, a_aA};
    const uint32_t baddr[3] = {a_k, a_k, a_k + 12288};
#pragma unroll
    for (int pass = 0; pass < 3; pass++) {
      const int l15 = lane & 15;
      const int ahi = (lane >> 4) << 4;
      const int rowA = w * 16 + l15;
      const uint32_t a_base = aaddr[pass] + rowA * 128;
      const int aswz = (rowA & 7) << 4;
      const int bl = lane & 7;
      const int bhi = (lane & 8) << 1;
#pragma unroll
      for (int kt = 0; kt < 4; kt++) {
        uint32_t a0, a1, a2, a3;
        LDSM_X4(a0, a1, a2, a3, a_base + ((kt * 32 + ahi) ^ aswz));
#pragma unroll
        for (int nt = 0; nt < 12; nt++) {
          uint32_t b0, b1;
          LDSM_X2(b0, b1, baddr[pass] + SW(nt * 8 + bl, kt * 32 + bhi));
          MMA16816(lacc[nt], a0, a1, a2, a3, b0, b1);
        }
      }
    }
  }
  __syncthreads();

  float* sl = (float*)(sm + O_Q);
  {
#pragma unroll
    for (int nt = 0; nt < 12; nt++) {
      int col = nt * 8 + tg * 2;
      float bv0 = __ldg(lm_b + col), bv1 = __ldg(lm_b + col + 1);
      float o00 = lacc[nt][0] + bv0, o01 = lacc[nt][1] + bv1;
      float o10 = lacc[nt][2] + bv0, o11 = lacc[nt][3] + bv1;
      sl[r0 * 96 + col] = o00;
      sl[r0 * 96 + col + 1] = o01;
      sl[(r0 + 8) * 96 + col] = o10;
      sl[(r0 + 8) * 96 + col + 1] = o11;
      if (write_logits) {
        float* ob = out + (size_t)(b * 128 + r0) * 96 + col;
        ob[0] = o00; ob[1] = o01;
        ob[8 * 96] = o10; ob[8 * 96 + 1] = o11;
      }
    }
  }
  __syncthreads();

  // ---- loss ----
  {
    int r = tid >> 1, p = tid & 1;
    const float* row = sl + r * 96 + p * 48;
    float m = -1e30f;
#pragma unroll
    for (int j = 0; j < 48; j++) m = fmaxf(m, row[j]);
    m = fmaxf(m, __shfl_xor_sync(0xffffffffu, m, 1));
    float se = 0.f;
#pragma unroll
    for (int j = 0; j < 48; j++) se += __expf(row[j] - m);
    se += __shfl_xor_sync(0xffffffffu, se, 1);
    float lse = m + logf(se);
    int tgt = targets[b * 128 + r];
    float contrib = 0.f;
    int rel = tgt - p * 48;
    if (rel >= 0 && rel < 48) contrib = row[rel] - lse;
    contrib += __shfl_xor_sync(0xffffffffu, contrib, 1);
    if (p == 0) sred[r] = contrib;
  }
  __syncthreads();
  if (tid < 128) {
    float v = sred[tid];
#pragma unroll
    for (int o = 16; o; o >>= 1) v += __shfl_xor_sync(0xffffffffu, v, o);
    if ((tid & 31) == 0) sred[128 + (tid >> 5)] = v;
  }
  __syncthreads();
  if (tid == 0)
    g_partial[b] = sred[128] + sred[129] + sred[130] + sred[131];
}

__global__ void loss_reduce_kernel(float* __restrict__ dst) {
  __shared__ float sh[8];
  float v = 0.f;
  for (int i = threadIdx.x; i < NCTAS; i += NTHREADS) v += g_partial[i];
#pragma unroll
  for (int o = 16; o; o >>= 1) v += __shfl_xor_sync(0xffffffffu, v, o);
  if ((threadIdx.x & 31) == 0) sh[threadIdx.x >> 5] = v;
  __syncthreads();
  if (threadIdx.x == 0) {
    float s = 0.f;
    for (int w = 0; w < 8; w++) s += sh[w];
    dst[0] = -s / (float)(4096 * 64);
  }
}

extern "C" void kernel_launch(void* const* d_in, const int* in_sizes, int n_in,
                              void* d_out, int out_size) {
  const int* idx = (const int*)d_in[0];
  const int* targets = (const int*)d_in[1];
  const float* tok_emb = (const float*)d_in[2];
  const float* pos_emb = (const float*)d_in[3];
  const float* ln1_g = (const float*)d_in[4];
  const float* ln1_b = (const float*)d_in[5];
  const float* wq = (const float*)d_in[6];
  const float* wk = (const float*)d_in[7];
  const float* wv = (const float*)d_in[8];
  const float* wo = (const float*)d_in[9];
  const float* bo = (const float*)d_in[10];
  const float* ln2_g = (const float*)d_in[11];
  const float* ln2_b = (const float*)d_in[12];
  const float* w1 = (const float*)d_in[13];
  const float* b1 = (const float*)d_in[14];
  const float* w2 = (const float*)d_in[15];
  const float* b2 = (const float*)d_in[16];
  const float* lnf_g = (const float*)d_in[17];
  const float* lnf_b = (const float*)d_in[18];
  const float* lm_w = (const float*)d_in[19];
  const float* lm_b = (const float*)d_in[20];
  float* out = (float*)d_out;

  cudaFuncSetAttribute(slm_kernel, cudaFuncAttributeMaxDynamicSharedMemorySize,
                       SMEM_BYTES);

  prep_kernel<<<792, 256>>>(wq, wk, wv, wo, w1, w2, lm_w);

  int write_logits = (out_size >= BTV) ? 1 : 0;
  slm_kernel<<<NCTAS, NTHREADS, SMEM_BYTES>>>(
      idx, targets, tok_emb, pos_emb, ln1_g, ln1_b, bo, ln2_g, ln2_b, b1, b2,
      lnf_g, lnf_b, lm_b, out, write_logits);

  if (out_size > BTV)
    loss_reduce_kernel<<<1, NTHREADS>>>(out + BTV);
  else if (out_size < BTV)
    loss_reduce_kernel<<<1, NTHREADS>>>(out);
}

// round 15
// speedup vs baseline: 1.5863x; 1.5863x over previous
#include <cuda_runtime.h>
#include <cuda_fp16.h>
#include <stdint.h>
#include <math.h>

#define NTHREADS 256
#define NCTAS 2048
#define BTV (4096 * 64 * 96)

#define O_XS 0
#define O_AA 34816
#define O_B 51200
#define O_Q 59392
#define O_K 75776
#define O_V 92160
#define O_SRED 108544
#define SMEM_BYTES 110592

#define SW(r, inner) ((r) * 128 + ((inner) ^ (((r) & 7) << 4)))

__device__ __align__(16) __half g_wqkv[49152];
__device__ __align__(16) __half g_wo[16384];
__device__ __align__(16) __half g_w1[65536];
__device__ __align__(16) __half g_w2[65536];
__device__ __align__(16) __half g_lmh[6144];
__device__ __align__(16) __half g_lml[6144];
__device__ float g_partial[NCTAS];

__device__ __forceinline__ uint32_t smem_u32(const void* p) {
  uint32_t a;
  asm("{ .reg .u64 t; cvta.to.shared.u64 t, %1; cvt.u32.u64 %0, t; }"
      : "=r"(a) : "l"(p));
  return a;
}
__device__ __forceinline__ uint32_t f2h2(float x, float y) {
  __half2 h = __floats2half2_rn(x, y);
  return *(uint32_t*)&h;
}

#define CP_WAIT_ALL asm volatile("cp.async.wait_all;" ::: "memory")

// async weight staging: 64x64 fp16 tile -> swizzled smem via LDGSTS
__device__ __forceinline__ void stageB_async(const __half* __restrict__ g,
                                             uint32_t s, int tid) {
  const char* src = (const char*)g;
  for (int i = tid; i < 512; i += NTHREADS) {
    int n = i >> 3, u = (i & 7) * 16;
    asm volatile("cp.async.ca.shared.global [%0], [%1], 16;" ::
                     "r"(s + SW(n, u)),
                 "l"(src + i * 16) : "memory");
  }
}
__device__ __forceinline__ void stageB96_async(const __half* __restrict__ g,
                                               uint32_t s, int tid) {
  const char* src = (const char*)g;
  for (int i = tid; i < 768; i += NTHREADS) {
    int n = i >> 3, u = (i & 7) * 16;
    asm volatile("cp.async.ca.shared.global [%0], [%1], 16;" ::
                     "r"(s + SW(n, u)),
                 "l"(src + i * 16) : "memory");
  }
}

#define LDSM_X4(a0, a1, a2, a3, addr)                                        \
  asm volatile("ldmatrix.sync.aligned.m8n8.x4.shared.b16 {%0,%1,%2,%3}, [%4];" \
               : "=r"(a0), "=r"(a1), "=r"(a2), "=r"(a3) : "r"(addr))
#define LDSM_X2(b0, b1, addr)                                                \
  asm volatile("ldmatrix.sync.aligned.m8n8.x2.shared.b16 {%0,%1}, [%2];"     \
               : "=r"(b0), "=r"(b1) : "r"(addr))
#define LDSM_X4T(a0, a1, a2, a3, addr)                                       \
  asm volatile(                                                              \
      "ldmatrix.sync.aligned.m8n8.x4.trans.shared.b16 {%0,%1,%2,%3}, [%4];"  \
      : "=r"(a0), "=r"(a1), "=r"(a2), "=r"(a3) : "r"(addr))
#define MMA16816(c, a0, a1, a2, a3, b0, b1)                                  \
  asm volatile(                                                              \
      "mma.sync.aligned.m16n8k16.row.col.f32.f16.f16.f32 "                   \
      "{%0,%1,%2,%3}, {%4,%5,%6,%7}, {%8,%9}, {%0,%1,%2,%3};"                \
      : "+f"((c)[0]), "+f"((c)[1]), "+f"((c)[2]), "+f"((c)[3])               \
      : "r"(a0), "r"(a1), "r"(a2), "r"(a3), "r"(b0), "r"(b1))

// 128x64x64 GEMM (x2 B loads — proven fastest form)
__device__ __forceinline__ void gemm_core(uint32_t a_addr, uint32_t b_addr,
                                          int w, int lane, float acc[8][4]) {
#pragma unroll
  for (int nt = 0; nt < 8; nt++)
#pragma unroll
    for (int e = 0; e < 4; e++) acc[nt][e] = 0.f;
  const int l15 = lane & 15;
  const int ahi = (lane >> 4) << 4;
  const int rowA = w * 16 + l15;
  const uint32_t a_base = a_addr + rowA * 128;
  const int aswz = (rowA & 7) << 4;
  const int bl = lane & 7;
  const int bhi = (lane & 8) << 1;
#pragma unroll
  for (int kt = 0; kt < 4; kt++) {
    uint32_t a0, a1, a2, a3;
    LDSM_X4(a0, a1, a2, a3, a_base + ((kt * 32 + ahi) ^ aswz));
#pragma unroll
    for (int nt = 0; nt < 8; nt++) {
      uint32_t b0, b1;
      LDSM_X2(b0, b1, b_addr + SW(nt * 8 + bl, kt * 32 + bhi));
      MMA16816(acc[nt], a0, a1, a2, a3, b0, b1);
    }
  }
}

// 128x96x64 accumulate pass (LM head)
__device__ __forceinline__ void lm_pass(uint32_t a_addr, uint32_t b_addr,
                                        int w, int lane, float acc[12][4]) {
  const int l15 = lane & 15;
  const int ahi = (lane >> 4) << 4;
  const int rowA = w * 16 + l15;
  const uint32_t a_base = a_addr + rowA * 128;
  const int aswz = (rowA & 7) << 4;
  const int bl = lane & 7;
  const int bhi = (lane & 8) << 1;
#pragma unroll
  for (int kt = 0; kt < 4; kt++) {
    uint32_t a0, a1, a2, a3;
    LDSM_X4(a0, a1, a2, a3, a_base + ((kt * 32 + ahi) ^ aswz));
#pragma unroll
    for (int nt = 0; nt < 12; nt++) {
      uint32_t b0, b1;
      LDSM_X2(b0, b1, b_addr + SW(nt * 8 + bl, kt * 32 + bhi));
      MMA16816(acc[nt], a0, a1, a2, a3, b0, b1);
    }
  }
}

// LayerNorm of xs row -> v[64] (128 threads, proven form)
__device__ __forceinline__ void ln_row(const float* row, float* v,
                                       const float* __restrict__ g,
                                       const float* __restrict__ b) {
  float s = 0.f, ss = 0.f;
#pragma unroll
  for (int i = 0; i < 16; i++) {
    float4 a = *(const float4*)(row + i * 4);
    v[i * 4] = a.x; v[i * 4 + 1] = a.y; v[i * 4 + 2] = a.z; v[i * 4 + 3] = a.w;
    s += a.x + a.y + a.z + a.w;
    ss += a.x * a.x + a.y * a.y + a.z * a.z + a.w * a.w;
  }
  float mean = s * 0.015625f;
  float inv = rsqrtf(ss * 0.015625f - mean * mean + 1e-5f);
#pragma unroll
  for (int c = 0; c < 64; c++)
    v[c] = (v[c] - mean) * inv * __ldg(g + c) + __ldg(b + c);
}

__device__ __forceinline__ void row_to_A(const float* v, char* aAc, int r) {
#pragma unroll
  for (int q8 = 0; q8 < 8; q8++) {
    uint32_t h[4];
#pragma unroll
    for (int e = 0; e < 4; e++)
      h[e] = f2h2(v[q8 * 8 + e * 2], v[q8 * 8 + e * 2 + 1]);
    *(uint4*)(aAc + SW(r, q8 * 16)) = *(uint4*)h;
  }
}

// ---------------- prep ----------------------------------------------------
__global__ void prep_kernel(const float* __restrict__ wq,
                            const float* __restrict__ wk,
                            const float* __restrict__ wv,
                            const float* __restrict__ wo,
                            const float* __restrict__ w1,
                            const float* __restrict__ w2,
                            const float* __restrict__ lm_w) {
  int i = blockIdx.x * blockDim.x + threadIdx.x;
  if (i < 49152) {
    int l = i / 12288, rr = i % 12288;
    int m = rr / 4096, r2 = rr % 4096;
    int n = r2 >> 6, k = r2 & 63;
    int h = n >> 4, s = n & 15;
    const float* src = (m == 0) ? wq : (m == 1) ? wk : wv;
    g_wqkv[i] = __float2half(src[l * 4096 + h * 1024 + k * 16 + s]);
  } else if (i < 65536) {
    int j = i - 49152;
    int l = j >> 12, n = (j >> 6) & 63, k = j & 63;
    g_wo[j] = __float2half(wo[l * 4096 + k * 64 + n]);
  } else if (i < 131072) {
    int j = i - 65536;
    int lj = j >> 12, n = (j >> 6) & 63, k = j & 63;
    int l = lj >> 2, jj = lj & 3;
    g_w1[j] = __float2half(w1[l * 16384 + k * 256 + jj * 64 + n]);
  } else if (i < 196608) {
    int j = i - 131072;
    int lj = j >> 12, n = (j >> 6) & 63, k = j & 63;
    int l = lj >> 2, jj = lj & 3;
    g_w2[j] = __float2half(w2[l * 16384 + (jj * 64 + k) * 64 + n]);
  } else if (i < 202752) {
    int j = i - 196608;
    int n = j >> 6, k = j & 63;
    float v = lm_w[k * 96 + n];
    __half hi = __float2half(v);
    g_lmh[j] = hi;
    g_lml[j] = __float2half(v - __half2float(hi));
  }
}

// ---------------- main fused kernel: 1 CTA = 2 sequences ------------------
__global__ void __launch_bounds__(NTHREADS, 2) slm_kernel(
    const int* __restrict__ idx, const int* __restrict__ targets,
    const float* __restrict__ tok_emb, const float* __restrict__ pos_emb,
    const float* __restrict__ ln1_g, const float* __restrict__ ln1_b,
    const float* __restrict__ bo, const float* __restrict__ ln2_g,
    const float* __restrict__ ln2_b, const float* __restrict__ b1,
    const float* __restrict__ b2, const float* __restrict__ lnf_g,
    const float* __restrict__ lnf_b, const float* __restrict__ lm_b,
    float* __restrict__ out, int write_logits) {
  extern __shared__ char sm[];
  float* xs = (float*)(sm + O_XS);
  char* aAc = sm + O_AA;
  float* sred = (float*)(sm + O_SRED);
  const int b = blockIdx.x;
  const int tid = threadIdx.x;
  const int w = tid >> 5, lane = tid & 31;
  const int g = lane >> 2, tg = lane & 3;
  const int r0 = w * 16 + g;
  const uint32_t smb = smem_u32(sm);
  const uint32_t a_aA = smb + O_AA, a_B = smb + O_B;
  const uint32_t a_q = smb + O_Q, a_k = smb + O_K, a_v = smb + O_V;

  for (int i = tid; i < 8192; i += NTHREADS) {
    int r = i >> 6, c = i & 63;
    xs[r * 68 + c] =
        tok_emb[idx[b * 128 + r] * 64 + c] + pos_emb[(r & 63) * 64 + c];
  }
  __syncthreads();

  float acc[8][4];

  for (int l = 0; l < 4; l++) {
    // ---- ln1 -> A; prestage wq->B, wk->O_V(temp) (async) ----
    stageB_async(g_wqkv + (l * 3 + 0) * 4096, a_B, tid);
    stageB_async(g_wqkv + (l * 3 + 1) * 4096, a_v, tid);
    if (tid < 128) {
      float v[64];
      ln_row(xs + tid * 68, v, ln1_g + l * 64, ln1_b + l * 64);
      row_to_A(v, aAc, tid);
    }
    CP_WAIT_ALL;
    __syncthreads();
    // ---- Q GEMM (B=wq) ----
    gemm_core(a_aA, a_B, w, lane, acc);
#pragma unroll
    for (int nt = 0; nt < 8; nt++) {
      int col = nt * 8 + tg * 2;
      *(uint32_t*)(sm + O_Q + SW(r0, col * 2)) = f2h2(acc[nt][0], acc[nt][1]);
      *(uint32_t*)(sm + O_Q + SW(r0 + 8, col * 2)) =
          f2h2(acc[nt][2], acc[nt][3]);
    }
    __syncthreads();
    // ---- K GEMM (B=wk in O_V temp); stage wv->B meanwhile ----
    stageB_async(g_wqkv + (l * 3 + 2) * 4096, a_B, tid);
    gemm_core(a_aA, a_v, w, lane, acc);
#pragma unroll
    for (int nt = 0; nt < 8; nt++) {
      int col = nt * 8 + tg * 2;
      *(uint32_t*)(sm + O_K + SW(r0, col * 2)) = f2h2(acc[nt][0], acc[nt][1]);
      *(uint32_t*)(sm + O_K + SW(r0 + 8, col * 2)) =
          f2h2(acc[nt][2], acc[nt][3]);
    }
    CP_WAIT_ALL;
    __syncthreads();
    // ---- V GEMM (B=wv), overwrites wk temp in O_V ----
    gemm_core(a_aA, a_B, w, lane, acc);
#pragma unroll
    for (int nt = 0; nt < 8; nt++) {
      int col = nt * 8 + tg * 2;
      *(uint32_t*)(sm + O_V + SW(r0, col * 2)) = f2h2(acc[nt][0], acc[nt][1]);
      *(uint32_t*)(sm + O_V + SW(r0 + 8, col * 2)) =
          f2h2(acc[nt][2], acc[nt][3]);
    }
    __syncthreads();
    // ---- attention: warp = (seq, head); balanced causal skip ----
    stageB_async(g_wo + l * 4096, a_B, tid);
    {
      const int bl = lane & 7;
      const int l15 = lane & 15;
      const int ahi = (lane >> 4) << 4;
      const int bhi = (lane & 8) << 1;
      const int vgrp = lane >> 4;
      const int seq0a = (w >> 2) * 64;
      const int h = w & 3;
      const int hb = h * 32;
#pragma unroll
      for (int mi = 0; mi < 4; mi++) {
        const int rowA = seq0a + mi * 16 + l15;
        uint32_t a0, a1, a2, a3;
        LDSM_X4(a0, a1, a2, a3,
                a_q + rowA * 128 + ((hb + ahi) ^ ((rowA & 7) << 4)));
        const int NT = 2 * (mi + 1);
        float S[8][4];
#pragma unroll
        for (int nt = 0; nt < 8; nt++) {
          if (nt >= NT) break;
#pragma unroll
          for (int e = 0; e < 4; e++) S[nt][e] = 0.f;
          uint32_t b0, b1;
          LDSM_X2(b0, b1, a_k + SW(seq0a + nt * 8 + bl, hb + bhi));
          MMA16816(S[nt], a0, a1, a2, a3, b0, b1);
        }
        const int tlo = mi * 16 + g;
        float mx0 = -1e30f, mx1 = -1e30f;
#pragma unroll
        for (int nt = 0; nt < 8; nt++) {
          if (nt >= NT) break;
          int c0 = nt * 8 + tg * 2;
          S[nt][0] = (c0 <= tlo) ? S[nt][0] * 0.25f : -1e30f;
          S[nt][1] = (c0 + 1 <= tlo) ? S[nt][1] * 0.25f : -1e30f;
          S[nt][2] = (c0 <= tlo + 8) ? S[nt][2] * 0.25f : -1e30f;
          S[nt][3] = (c0 + 1 <= tlo + 8) ? S[nt][3] * 0.25f : -1e30f;
          mx0 = fmaxf(mx0, fmaxf(S[nt][0], S[nt][1]));
          mx1 = fmaxf(mx1, fmaxf(S[nt][2], S[nt][3]));
        }
        mx0 = fmaxf(mx0, __shfl_xor_sync(0xffffffffu, mx0, 1));
        mx0 = fmaxf(mx0, __shfl_xor_sync(0xffffffffu, mx0, 2));
        mx1 = fmaxf(mx1, __shfl_xor_sync(0xffffffffu, mx1, 1));
        mx1 = fmaxf(mx1, __shfl_xor_sync(0xffffffffu, mx1, 2));
        float sum0 = 0.f, sum1 = 0.f;
#pragma unroll
        for (int nt = 0; nt < 8; nt++) {
          if (nt >= NT) break;
          S[nt][0] = __expf(S[nt][0] - mx0);
          S[nt][1] = __expf(S[nt][1] - mx0);
          S[nt][2] = __expf(S[nt][2] - mx1);
          S[nt][3] = __expf(S[nt][3] - mx1);
          sum0 += S[nt][0] + S[nt][1];
          sum1 += S[nt][2] + S[nt][3];
        }
        sum0 += __shfl_xor_sync(0xffffffffu, sum0, 1);
        sum0 += __shfl_xor_sync(0xffffffffu, sum0, 2);
        sum1 += __shfl_xor_sync(0xffffffffu, sum1, 1);
        sum1 += __shfl_xor_sync(0xffffffffu, sum1, 2);
        float ri0 = 1.f / sum0, ri1 = 1.f / sum1;
        float O[2][4];
#pragma unroll
        for (int nt = 0; nt < 2; nt++)
#pragma unroll
          for (int e = 0; e < 4; e++) O[nt][e] = 0.f;
#pragma unroll
        for (int kb = 0; kb < 4; kb++) {
          if (kb > mi) break;
          uint32_t p0 = f2h2(S[2 * kb][0] * ri0, S[2 * kb][1] * ri0);
          uint32_t p1 = f2h2(S[2 * kb][2] * ri1, S[2 * kb][3] * ri1);
          uint32_t p2 = f2h2(S[2 * kb + 1][0] * ri0, S[2 * kb + 1][1] * ri0);
          uint32_t p3 = f2h2(S[2 * kb + 1][2] * ri1, S[2 * kb + 1][3] * ri1);
          int ur = seq0a + kb * 16 + bl + ((lane & 8) ? 8 : 0);
          uint32_t b0, b1, b2, b3;
          LDSM_X4T(b0, b1, b2, b3, a_v + SW(ur, hb + vgrp * 16));
          MMA16816(O[0], p0, p1, p2, p3, b0, b1);
          MMA16816(O[1], p0, p1, p2, p3, b2, b3);
        }
        const int orow = seq0a + mi * 16 + g;
#pragma unroll
        for (int nt = 0; nt < 2; nt++) {
          int col = h * 16 + nt * 8 + tg * 2;
          *(uint32_t*)(aAc + SW(orow, col * 2)) = f2h2(O[nt][0], O[nt][1]);
          *(uint32_t*)(aAc + SW(orow + 8, col * 2)) = f2h2(O[nt][2], O[nt][3]);
        }
      }
    }
    CP_WAIT_ALL;
    __syncthreads();
    // ---- WO GEMM (wo prestaged): xs += d + bo ----
    gemm_core(a_aA, a_B, w, lane, acc);
    {
      const float* bp = bo + l * 64;
#pragma unroll
      for (int nt = 0; nt < 8; nt++) {
        int col = nt * 8 + tg * 2;
        float bv0 = __ldg(bp + col), bv1 = __ldg(bp + col + 1);
        xs[r0 * 68 + col] += acc[nt][0] + bv0;
        xs[r0 * 68 + col + 1] += acc[nt][1] + bv1;
        xs[(r0 + 8) * 68 + col] += acc[nt][2] + bv0;
        xs[(r0 + 8) * 68 + col + 1] += acc[nt][3] + bv1;
      }
    }
    __syncthreads();
    // ---- ln2 -> A; prestage first MLP chunk (async) ----
    stageB_async(g_w1 + (l * 4) * 4096, a_B, tid);
    stageB_async(g_w2 + (l * 4) * 4096, a_k, tid);
    if (tid < 128) {
      float v[64];
      ln_row(xs + tid * 68, v, ln2_g + l * 64, ln2_b + l * 64);
      row_to_A(v, aAc, tid);
    }
    CP_WAIT_ALL;
    __syncthreads();
    // ---- MLP: double-buffered w1 (B / O_V), w2 (O_K halves) ----
    char* aMc = sm + O_Q;
    const uint32_t a_aM = a_q;
    for (int j = 0; j < 4; j++) {
      uint32_t a_w1 = (j & 1) ? a_v : a_B;
      uint32_t a_w2 = a_k + ((j & 1) ? 8192 : 0);
      gemm_core(a_aA, a_w1, w, lane, acc);
      {
        const float* bp = b1 + l * 256 + j * 64;
#pragma unroll
        for (int nt = 0; nt < 8; nt++) {
          int col = nt * 8 + tg * 2;
          float bv0 = __ldg(bp + col), bv1 = __ldg(bp + col + 1);
          *(uint32_t*)(aMc + SW(r0, col * 2)) = f2h2(
              fmaxf(acc[nt][0] + bv0, 0.f), fmaxf(acc[nt][1] + bv1, 0.f));
          *(uint32_t*)(aMc + SW(r0 + 8, col * 2)) = f2h2(
              fmaxf(acc[nt][2] + bv0, 0.f), fmaxf(acc[nt][3] + bv1, 0.f));
        }
      }
      if (j < 3)
        stageB_async(g_w1 + (l * 4 + j + 1) * 4096, (j & 1) ? a_B : a_v, tid);
      CP_WAIT_ALL;
      __syncthreads();
      gemm_core(a_aM, a_w2, w, lane, acc);
      {
        const float* bp = (j == 3) ? (b2 + l * 64) : nullptr;
#pragma unroll
        for (int nt = 0; nt < 8; nt++) {
          int col = nt * 8 + tg * 2;
          float bv0 = bp ? __ldg(bp + col) : 0.f;
          float bv1 = bp ? __ldg(bp + col + 1) : 0.f;
          xs[r0 * 68 + col] += acc[nt][0] + bv0;
          xs[r0 * 68 + col + 1] += acc[nt][1] + bv1;
          xs[(r0 + 8) * 68 + col] += acc[nt][2] + bv0;
          xs[(r0 + 8) * 68 + col + 1] += acc[nt][3] + bv1;
        }
      }
      if (j < 3)
        stageB_async(g_w2 + (l * 4 + j + 1) * 4096,
                     a_k + ((j & 1) ? 0 : 8192), tid);
      CP_WAIT_ALL;
      __syncthreads();
    }
  }

  // ---- final LN -> split fp16 operands Ah @ O_AA, Al @ O_Q ----
  stageB96_async(g_lmh, a_k, tid);
  stageB96_async(g_lml, a_k + 12288, tid);
  if (tid < 128) {
    float v[64];
    ln_row(xs + tid * 68, v, lnf_g, lnf_b);
    char* Alc = sm + O_Q;
#pragma unroll
    for (int q8 = 0; q8 < 8; q8++) {
      uint32_t hh[4], hl[4];
#pragma unroll
      for (int e = 0; e < 4; e++) {
        float v0 = v[q8 * 8 + e * 2], v1 = v[q8 * 8 + e * 2 + 1];
        hh[e] = f2h2(v0, v1);
        __half2 hi2 = *(__half2*)&hh[e];
        float2 hif = __half22float2(hi2);
        hl[e] = f2h2(v0 - hif.x, v1 - hif.y);
      }
      *(uint4*)(aAc + SW(tid, q8 * 16)) = *(uint4*)hh;
      *(uint4*)(Alc + SW(tid, q8 * 16)) = *(uint4*)hl;
    }
  }
  CP_WAIT_ALL;
  __syncthreads();

  // ---- LM head: 128x96x64 split GEMM on tensor cores ----
  float lacc[12][4];
#pragma unroll
  for (int nt = 0; nt < 12; nt++)
#pragma unroll
    for (int e = 0; e < 4; e++) lacc[nt][e] = 0.f;
  lm_pass(a_aA, a_k, w, lane, lacc);          // Ah @ Bh
  lm_pass(a_q, a_k, w, lane, lacc);           // Al @ Bh
  lm_pass(a_aA, a_k + 12288, w, lane, lacc);  // Ah @ Bl
  __syncthreads();

  float* sl = (float*)(sm + O_Q);
  {
#pragma unroll
    for (int nt = 0; nt < 12; nt++) {
      int col = nt * 8 + tg * 2;
      float bv0 = __ldg(lm_b + col), bv1 = __ldg(lm_b + col + 1);
      float o00 = lacc[nt][0] + bv0, o01 = lacc[nt][1] + bv1;
      float o10 = lacc[nt][2] + bv0, o11 = lacc[nt][3] + bv1;
      sl[r0 * 96 + col] = o00;
      sl[r0 * 96 + col + 1] = o01;
      sl[(r0 + 8) * 96 + col] = o10;
      sl[(r0 + 8) * 96 + col + 1] = o11;
      if (write_logits) {
        float* ob = out + (size_t)(b * 128 + r0) * 96 + col;
        ob[0] = o00; ob[1] = o01;
        ob[8 * 96] = o10; ob[8 * 96 + 1] = o11;
      }
    }
  }
  __syncthreads();

  // ---- loss ----
  {
    int r = tid >> 1, p = tid & 1;
    const float* row = sl + r * 96 + p * 48;
    float m = -1e30f;
#pragma unroll
    for (int j = 0; j < 48; j++) m = fmaxf(m, row[j]);
    m = fmaxf(m, __shfl_xor_sync(0xffffffffu, m, 1));
    float se = 0.f;
#pragma unroll
    for (int j = 0; j < 48; j++) se += __expf(row[j] - m);
    se += __shfl_xor_sync(0xffffffffu, se, 1);
    float lse = m + logf(se);
    int tgt = targets[b * 128 + r];
    float contrib = 0.f;
    int rel = tgt - p * 48;
    if (rel >= 0 && rel < 48) contrib = row[rel] - lse;
    contrib += __shfl_xor_sync(0xffffffffu, contrib, 1);
    if (p == 0) sred[r] = contrib;
  }
  __syncthreads();
  if (tid < 128) {
    float v = sred[tid];
#pragma unroll
    for (int o = 16; o; o >>= 1) v += __shfl_xor_sync(0xffffffffu, v, o);
    if ((tid & 31) == 0) sred[128 + (tid >> 5)] = v;
  }
  __syncthreads();
  if (tid == 0)
    g_partial[b] = sred[128] + sred[129] + sred[130] + sred[131];
}

__global__ void loss_reduce_kernel(float* __restrict__ dst) {
  __shared__ float sh[8];
  float v = 0.f;
  for (int i = threadIdx.x; i < NCTAS; i += NTHREADS) v += g_partial[i];
#pragma unroll
  for (int o = 16; o; o >>= 1) v += __shfl_xor_sync(0xffffffffu, v, o);
  if ((threadIdx.x & 31) == 0) sh[threadIdx.x >> 5] = v;
  __syncthreads();
  if (threadIdx.x == 0) {
    float s = 0.f;
    for (int w = 0; w < 8; w++) s += sh[w];
    dst[0] = -s / (float)(4096 * 64);
  }
}

extern "C" void kernel_launch(void* const* d_in, const int* in_sizes, int n_in,
                              void* d_out, int out_size) {
  const int* idx = (const int*)d_in[0];
  const int* targets = (const int*)d_in[1];
  const float* tok_emb = (const float*)d_in[2];
  const float* pos_emb = (const float*)d_in[3];
  const float* ln1_g = (const float*)d_in[4];
  const float* ln1_b = (const float*)d_in[5];
  const float* wq = (const float*)d_in[6];
  const float* wk = (const float*)d_in[7];
  const float* wv = (const float*)d_in[8];
  const float* wo = (const float*)d_in[9];
  const float* bo = (const float*)d_in[10];
  const float* ln2_g = (const float*)d_in[11];
  const float* ln2_b = (const float*)d_in[12];
  const float* w1 = (const float*)d_in[13];
  const float* b1 = (const float*)d_in[14];
  const float* w2 = (const float*)d_in[15];
  const float* b2 = (const float*)d_in[16];
  const float* lnf_g = (const float*)d_in[17];
  const float* lnf_b = (const float*)d_in[18];
  const float* lm_w = (const float*)d_in[19];
  const float* lm_b = (const float*)d_in[20];
  float* out = (float*)d_out;

  cudaFuncSetAttribute(slm_kernel, cudaFuncAttributeMaxDynamicSharedMemorySize,
                       SMEM_BYTES);

  prep_kernel<<<792, 256>>>(wq, wk, wv, wo, w1, w2, lm_w);

  int write_logits = (out_size >= BTV) ? 1 : 0;
  slm_kernel<<<NCTAS, NTHREADS, SMEM_BYTES>>>(
      idx, targets, tok_emb, pos_emb, ln1_g, ln1_b, bo, ln2_g, ln2_b, b1, b2,
      lnf_g, lnf_b, lm_b, out, write_logits);

  if (out_size > BTV)
    loss_reduce_kernel<<<1, NTHREADS>>>(out + BTV);
  else if (out_size < BTV)
    loss_reduce_kernel<<<1, NTHREADS>>>(out);
}

// round 16
// speedup vs baseline: 1.6062x; 1.0126x over previous
#include <cuda_runtime.h>
#include <cuda_fp16.h>
#include <stdint.h>
#include <math.h>

#define NTHREADS 256
#define NCTAS 2048
#define BTV (4096 * 64 * 96)

#define O_XS 0
#define O_AA 34816
#define O_B 51200
#define O_Q 59392
#define O_K 75776
#define O_V 92160
#define O_SRED 108544
#define SMEM_BYTES 110592

#define SW(r, inner) ((r) * 128 + ((inner) ^ (((r) & 7) << 4)))

__device__ __align__(16) __half g_wqkv[49152];
__device__ __align__(16) __half g_wo[16384];
__device__ __align__(16) __half g_w1[65536];
__device__ __align__(16) __half g_w2[65536];
__device__ __align__(16) __half g_lmh[6144];
__device__ __align__(16) __half g_lml[6144];
__device__ float g_partial[NCTAS];

__device__ __forceinline__ uint32_t smem_u32(const void* p) {
  uint32_t a;
  asm("{ .reg .u64 t; cvta.to.shared.u64 t, %1; cvt.u32.u64 %0, t; }"
      : "=r"(a) : "l"(p));
  return a;
}
__device__ __forceinline__ uint32_t f2h2(float x, float y) {
  __half2 h = __floats2half2_rn(x, y);
  return *(uint32_t*)&h;
}

#define CP_WAIT_ALL asm volatile("cp.async.wait_all;" ::: "memory")

__device__ __forceinline__ void stageB_async(const __half* __restrict__ g,
                                             uint32_t s, int tid) {
  const char* src = (const char*)g;
  for (int i = tid; i < 512; i += NTHREADS) {
    int n = i >> 3, u = (i & 7) * 16;
    asm volatile("cp.async.ca.shared.global [%0], [%1], 16;" ::
                     "r"(s + SW(n, u)),
                 "l"(src + i * 16) : "memory");
  }
}
__device__ __forceinline__ void stageB96_async(const __half* __restrict__ g,
                                               uint32_t s, int tid) {
  const char* src = (const char*)g;
  for (int i = tid; i < 768; i += NTHREADS) {
    int n = i >> 3, u = (i & 7) * 16;
    asm volatile("cp.async.ca.shared.global [%0], [%1], 16;" ::
                     "r"(s + SW(n, u)),
                 "l"(src + i * 16) : "memory");
  }
}

#define LDSM_X4(a0, a1, a2, a3, addr)                                        \
  asm volatile("ldmatrix.sync.aligned.m8n8.x4.shared.b16 {%0,%1,%2,%3}, [%4];" \
               : "=r"(a0), "=r"(a1), "=r"(a2), "=r"(a3) : "r"(addr))
#define LDSM_X2(b0, b1, addr)                                                \
  asm volatile("ldmatrix.sync.aligned.m8n8.x2.shared.b16 {%0,%1}, [%2];"     \
               : "=r"(b0), "=r"(b1) : "r"(addr))
#define LDSM_X4T(a0, a1, a2, a3, addr)                                       \
  asm volatile(                                                              \
      "ldmatrix.sync.aligned.m8n8.x4.trans.shared.b16 {%0,%1,%2,%3}, [%4];"  \
      : "=r"(a0), "=r"(a1), "=r"(a2), "=r"(a3) : "r"(addr))
#define MMA16816(c, a0, a1, a2, a3, b0, b1)                                  \
  asm volatile(                                                              \
      "mma.sync.aligned.m16n8k16.row.col.f32.f16.f16.f32 "                   \
      "{%0,%1,%2,%3}, {%4,%5,%6,%7}, {%8,%9}, {%0,%1,%2,%3};"                \
      : "+f"((c)[0]), "+f"((c)[1]), "+f"((c)[2]), "+f"((c)[3])               \
      : "r"(a0), "r"(a1), "r"(a2), "r"(a3), "r"(b0), "r"(b1))

// 128x64x64 GEMM (x2 B loads — proven fastest form)
__device__ __forceinline__ void gemm_core(uint32_t a_addr, uint32_t b_addr,
                                          int w, int lane, float acc[8][4]) {
#pragma unroll
  for (int nt = 0; nt < 8; nt++)
#pragma unroll
    for (int e = 0; e < 4; e++) acc[nt][e] = 0.f;
  const int l15 = lane & 15;
  const int ahi = (lane >> 4) << 4;
  const int rowA = w * 16 + l15;
  const uint32_t a_base = a_addr + rowA * 128;
  const int aswz = (rowA & 7) << 4;
  const int bl = lane & 7;
  const int bhi = (lane & 8) << 1;
#pragma unroll
  for (int kt = 0; kt < 4; kt++) {
    uint32_t a0, a1, a2, a3;
    LDSM_X4(a0, a1, a2, a3, a_base + ((kt * 32 + ahi) ^ aswz));
#pragma unroll
    for (int nt = 0; nt < 8; nt++) {
      uint32_t b0, b1;
      LDSM_X2(b0, b1, b_addr + SW(nt * 8 + bl, kt * 32 + bhi));
      MMA16816(acc[nt], a0, a1, a2, a3, b0, b1);
    }
  }
}

// 128x96x64 accumulate pass (LM head)
__device__ __forceinline__ void lm_pass(uint32_t a_addr, uint32_t b_addr,
                                        int w, int lane, float acc[12][4]) {
  const int l15 = lane & 15;
  const int ahi = (lane >> 4) << 4;
  const int rowA = w * 16 + l15;
  const uint32_t a_base = a_addr + rowA * 128;
  const int aswz = (rowA & 7) << 4;
  const int bl = lane & 7;
  const int bhi = (lane & 8) << 1;
#pragma unroll
  for (int kt = 0; kt < 4; kt++) {
    uint32_t a0, a1, a2, a3;
    LDSM_X4(a0, a1, a2, a3, a_base + ((kt * 32 + ahi) ^ aswz));
#pragma unroll
    for (int nt = 0; nt < 12; nt++) {
      uint32_t b0, b1;
      LDSM_X2(b0, b1, b_addr + SW(nt * 8 + bl, kt * 32 + bhi));
      MMA16816(acc[nt], a0, a1, a2, a3, b0, b1);
    }
  }
}

// LayerNorm of xs row -> v[64] (128 threads, proven form)
__device__ __forceinline__ void ln_row(const float* row, float* v,
                                       const float* __restrict__ g,
                                       const float* __restrict__ b) {
  float s = 0.f, ss = 0.f;
#pragma unroll
  for (int i = 0; i < 16; i++) {
    float4 a = *(const float4*)(row + i * 4);
    v[i * 4] = a.x; v[i * 4 + 1] = a.y; v[i * 4 + 2] = a.z; v[i * 4 + 3] = a.w;
    s += a.x + a.y + a.z + a.w;
    ss += a.x * a.x + a.y * a.y + a.z * a.z + a.w * a.w;
  }
  float mean = s * 0.015625f;
  float inv = rsqrtf(ss * 0.015625f - mean * mean + 1e-5f);
#pragma unroll
  for (int c = 0; c < 64; c++)
    v[c] = (v[c] - mean) * inv * __ldg(g + c) + __ldg(b + c);
}

__device__ __forceinline__ void row_to_A(const float* v, char* aAc, int r) {
#pragma unroll
  for (int q8 = 0; q8 < 8; q8++) {
    uint32_t h[4];
#pragma unroll
    for (int e = 0; e < 4; e++)
      h[e] = f2h2(v[q8 * 8 + e * 2], v[q8 * 8 + e * 2 + 1]);
    *(uint4*)(aAc + SW(r, q8 * 16)) = *(uint4*)h;
  }
}

// ---------------- prep ----------------------------------------------------
__global__ void prep_kernel(const float* __restrict__ wq,
                            const float* __restrict__ wk,
                            const float* __restrict__ wv,
                            const float* __restrict__ wo,
                            const float* __restrict__ w1,
                            const float* __restrict__ w2,
                            const float* __restrict__ lm_w) {
  int i = blockIdx.x * blockDim.x + threadIdx.x;
  if (i < 49152) {
    int l = i / 12288, rr = i % 12288;
    int m = rr / 4096, r2 = rr % 4096;
    int n = r2 >> 6, k = r2 & 63;
    int h = n >> 4, s = n & 15;
    const float* src = (m == 0) ? wq : (m == 1) ? wk : wv;
    g_wqkv[i] = __float2half(src[l * 4096 + h * 1024 + k * 16 + s]);
  } else if (i < 65536) {
    int j = i - 49152;
    int l = j >> 12, n = (j >> 6) & 63, k = j & 63;
    g_wo[j] = __float2half(wo[l * 4096 + k * 64 + n]);
  } else if (i < 131072) {
    int j = i - 65536;
    int lj = j >> 12, n = (j >> 6) & 63, k = j & 63;
    int l = lj >> 2, jj = lj & 3;
    g_w1[j] = __float2half(w1[l * 16384 + k * 256 + jj * 64 + n]);
  } else if (i < 196608) {
    int j = i - 131072;
    int lj = j >> 12, n = (j >> 6) & 63, k = j & 63;
    int l = lj >> 2, jj = lj & 3;
    g_w2[j] = __float2half(w2[l * 16384 + (jj * 64 + k) * 64 + n]);
  } else if (i < 202752) {
    int j = i - 196608;
    int n = j >> 6, k = j & 63;
    float v = lm_w[k * 96 + n];
    __half hi = __float2half(v);
    g_lmh[j] = hi;
    g_lml[j] = __float2half(v - __half2float(hi));
  }
}

// ---------------- main fused kernel: 1 CTA = 2 sequences ------------------
__global__ void __launch_bounds__(NTHREADS, 2) slm_kernel(
    const int* __restrict__ idx, const int* __restrict__ targets,
    const float* __restrict__ tok_emb, const float* __restrict__ pos_emb,
    const float* __restrict__ ln1_g, const float* __restrict__ ln1_b,
    const float* __restrict__ bo, const float* __restrict__ ln2_g,
    const float* __restrict__ ln2_b, const float* __restrict__ b1,
    const float* __restrict__ b2, const float* __restrict__ lnf_g,
    const float* __restrict__ lnf_b, const float* __restrict__ lm_b,
    float* __restrict__ out, int write_logits) {
  extern __shared__ char sm[];
  float* xs = (float*)(sm + O_XS);
  char* aAc = sm + O_AA;
  float* sred = (float*)(sm + O_SRED);
  const int b = blockIdx.x;
  const int tid = threadIdx.x;
  const int w = tid >> 5, lane = tid & 31;
  const int g = lane >> 2, tg = lane & 3;
  const int r0 = w * 16 + g;
  const uint32_t smb = smem_u32(sm);
  const uint32_t a_aA = smb + O_AA, a_B = smb + O_B;
  const uint32_t a_q = smb + O_Q, a_k = smb + O_K, a_v = smb + O_V;

  for (int i = tid; i < 8192; i += NTHREADS) {
    int r = i >> 6, c = i & 63;
    xs[r * 68 + c] =
        tok_emb[idx[b * 128 + r] * 64 + c] + pos_emb[(r & 63) * 64 + c];
  }
  __syncthreads();

  float acc[8][4];

  for (int l = 0; l < 4; l++) {
    // ---- ln1 -> A; prestage wq->B, wk->O_V(temp) (async) ----
    stageB_async(g_wqkv + (l * 3 + 0) * 4096, a_B, tid);
    stageB_async(g_wqkv + (l * 3 + 1) * 4096, a_v, tid);
    if (tid < 128) {
      float v[64];
      ln_row(xs + tid * 68, v, ln1_g + l * 64, ln1_b + l * 64);
      row_to_A(v, aAc, tid);
    }
    CP_WAIT_ALL;
    __syncthreads();
    // ---- Q GEMM (B=wq) ----
    gemm_core(a_aA, a_B, w, lane, acc);
#pragma unroll
    for (int nt = 0; nt < 8; nt++) {
      int col = nt * 8 + tg * 2;
      *(uint32_t*)(sm + O_Q + SW(r0, col * 2)) = f2h2(acc[nt][0], acc[nt][1]);
      *(uint32_t*)(sm + O_Q + SW(r0 + 8, col * 2)) =
          f2h2(acc[nt][2], acc[nt][3]);
    }
    __syncthreads();
    // ---- K GEMM (B=wk in O_V temp); stage wv->B meanwhile ----
    stageB_async(g_wqkv + (l * 3 + 2) * 4096, a_B, tid);
    gemm_core(a_aA, a_v, w, lane, acc);
#pragma unroll
    for (int nt = 0; nt < 8; nt++) {
      int col = nt * 8 + tg * 2;
      *(uint32_t*)(sm + O_K + SW(r0, col * 2)) = f2h2(acc[nt][0], acc[nt][1]);
      *(uint32_t*)(sm + O_K + SW(r0 + 8, col * 2)) =
          f2h2(acc[nt][2], acc[nt][3]);
    }
    CP_WAIT_ALL;
    __syncthreads();
    // ---- V GEMM (B=wv), overwrites wk temp in O_V ----
    gemm_core(a_aA, a_B, w, lane, acc);
#pragma unroll
    for (int nt = 0; nt < 8; nt++) {
      int col = nt * 8 + tg * 2;
      *(uint32_t*)(sm + O_V + SW(r0, col * 2)) = f2h2(acc[nt][0], acc[nt][1]);
      *(uint32_t*)(sm + O_V + SW(r0 + 8, col * 2)) =
          f2h2(acc[nt][2], acc[nt][3]);
    }
    __syncthreads();
    // ---- attention: warp = (seq, head); balanced causal skip ----
    stageB_async(g_wo + l * 4096, a_B, tid);
    {
      const int bl = lane & 7;
      const int l15 = lane & 15;
      const int ahi = (lane >> 4) << 4;
      const int bhi = (lane & 8) << 1;
      const int vgrp = lane >> 4;
      const int seq0a = (w >> 2) * 64;
      const int h = w & 3;
      const int hb = h * 32;
#pragma unroll
      for (int mi = 0; mi < 4; mi++) {
        const int rowA = seq0a + mi * 16 + l15;
        uint32_t a0, a1, a2, a3;
        LDSM_X4(a0, a1, a2, a3,
                a_q + rowA * 128 + ((hb + ahi) ^ ((rowA & 7) << 4)));
        const int NT = 2 * (mi + 1);
        float S[8][4];
#pragma unroll
        for (int nt = 0; nt < 8; nt++) {
          if (nt >= NT) break;
#pragma unroll
          for (int e = 0; e < 4; e++) S[nt][e] = 0.f;
          uint32_t b0, b1;
          LDSM_X2(b0, b1, a_k + SW(seq0a + nt * 8 + bl, hb + bhi));
          MMA16816(S[nt], a0, a1, a2, a3, b0, b1);
        }
        const int tlo = mi * 16 + g;
        float mx0 = -1e30f, mx1 = -1e30f;
#pragma unroll
        for (int nt = 0; nt < 8; nt++) {
          if (nt >= NT) break;
          int c0 = nt * 8 + tg * 2;
          S[nt][0] = (c0 <= tlo) ? S[nt][0] * 0.25f : -1e30f;
          S[nt][1] = (c0 + 1 <= tlo) ? S[nt][1] * 0.25f : -1e30f;
          S[nt][2] = (c0 <= tlo + 8) ? S[nt][2] * 0.25f : -1e30f;
          S[nt][3] = (c0 + 1 <= tlo + 8) ? S[nt][3] * 0.25f : -1e30f;
          mx0 = fmaxf(mx0, fmaxf(S[nt][0], S[nt][1]));
          mx1 = fmaxf(mx1, fmaxf(S[nt][2], S[nt][3]));
        }
        mx0 = fmaxf(mx0, __shfl_xor_sync(0xffffffffu, mx0, 1));
        mx0 = fmaxf(mx0, __shfl_xor_sync(0xffffffffu, mx0, 2));
        mx1 = fmaxf(mx1, __shfl_xor_sync(0xffffffffu, mx1, 1));
        mx1 = fmaxf(mx1, __shfl_xor_sync(0xffffffffu, mx1, 2));
        float sum0 = 0.f, sum1 = 0.f;
#pragma unroll
        for (int nt = 0; nt < 8; nt++) {
          if (nt >= NT) break;
          S[nt][0] = __expf(S[nt][0] - mx0);
          S[nt][1] = __expf(S[nt][1] - mx0);
          S[nt][2] = __expf(S[nt][2] - mx1);
          S[nt][3] = __expf(S[nt][3] - mx1);
          sum0 += S[nt][0] + S[nt][1];
          sum1 += S[nt][2] + S[nt][3];
        }
        sum0 += __shfl_xor_sync(0xffffffffu, sum0, 1);
        sum0 += __shfl_xor_sync(0xffffffffu, sum0, 2);
        sum1 += __shfl_xor_sync(0xffffffffu, sum1, 1);
        sum1 += __shfl_xor_sync(0xffffffffu, sum1, 2);
        float ri0 = 1.f / sum0, ri1 = 1.f / sum1;
        float O[2][4];
#pragma unroll
        for (int nt = 0; nt < 2; nt++)
#pragma unroll
          for (int e = 0; e < 4; e++) O[nt][e] = 0.f;
#pragma unroll
        for (int kb = 0; kb < 4; kb++) {
          if (kb > mi) break;
          uint32_t p0 = f2h2(S[2 * kb][0] * ri0, S[2 * kb][1] * ri0);
          uint32_t p1 = f2h2(S[2 * kb][2] * ri1, S[2 * kb][3] * ri1);
          uint32_t p2 = f2h2(S[2 * kb + 1][0] * ri0, S[2 * kb + 1][1] * ri0);
          uint32_t p3 = f2h2(S[2 * kb + 1][2] * ri1, S[2 * kb + 1][3] * ri1);
          int ur = seq0a + kb * 16 + bl + ((lane & 8) ? 8 : 0);
          uint32_t b0, b1, b2, b3;
          LDSM_X4T(b0, b1, b2, b3, a_v + SW(ur, hb + vgrp * 16));
          MMA16816(O[0], p0, p1, p2, p3, b0, b1);
          MMA16816(O[1], p0, p1, p2, p3, b2, b3);
        }
        const int orow = seq0a + mi * 16 + g;
#pragma unroll
        for (int nt = 0; nt < 2; nt++) {
          int col = h * 16 + nt * 8 + tg * 2;
          *(uint32_t*)(aAc + SW(orow, col * 2)) = f2h2(O[nt][0], O[nt][1]);
          *(uint32_t*)(aAc + SW(orow + 8, col * 2)) = f2h2(O[nt][2], O[nt][3]);
        }
      }
    }
    CP_WAIT_ALL;
    __syncthreads();
    // ---- WO GEMM (wo prestaged): xs += d + bo (float2 epilogue) ----
    gemm_core(a_aA, a_B, w, lane, acc);
    {
      const float* bp = bo + l * 64;
#pragma unroll
      for (int nt = 0; nt < 8; nt++) {
        int col = nt * 8 + tg * 2;
        float bv0 = __ldg(bp + col), bv1 = __ldg(bp + col + 1);
        float2* x0 = (float2*)(xs + r0 * 68 + col);
        float2* x1 = (float2*)(xs + (r0 + 8) * 68 + col);
        float2 v0 = *x0, v1 = *x1;
        v0.x += acc[nt][0] + bv0; v0.y += acc[nt][1] + bv1;
        v1.x += acc[nt][2] + bv0; v1.y += acc[nt][3] + bv1;
        *x0 = v0; *x1 = v1;
      }
    }
    __syncthreads();
    // ---- ln2 -> A; prestage first MLP chunk (async) ----
    stageB_async(g_w1 + (l * 4) * 4096, a_B, tid);
    stageB_async(g_w2 + (l * 4) * 4096, a_k, tid);
    if (tid < 128) {
      float v[64];
      ln_row(xs + tid * 68, v, ln2_g + l * 64, ln2_b + l * 64);
      row_to_A(v, aAc, tid);
    }
    CP_WAIT_ALL;
    __syncthreads();
    // ---- MLP: double-buffered w1 (B / O_V), w2 (O_K halves) ----
    char* aMc = sm + O_Q;
    const uint32_t a_aM = a_q;
    for (int j = 0; j < 4; j++) {
      uint32_t a_w1 = (j & 1) ? a_v : a_B;
      uint32_t a_w2 = a_k + ((j & 1) ? 8192 : 0);
      gemm_core(a_aA, a_w1, w, lane, acc);
      {
        const float* bp = b1 + l * 256 + j * 64;
#pragma unroll
        for (int nt = 0; nt < 8; nt++) {
          int col = nt * 8 + tg * 2;
          float bv0 = __ldg(bp + col), bv1 = __ldg(bp + col + 1);
          *(uint32_t*)(aMc + SW(r0, col * 2)) = f2h2(
              fmaxf(acc[nt][0] + bv0, 0.f), fmaxf(acc[nt][1] + bv1, 0.f));
          *(uint32_t*)(aMc + SW(r0 + 8, col * 2)) = f2h2(
              fmaxf(acc[nt][2] + bv0, 0.f), fmaxf(acc[nt][3] + bv1, 0.f));
        }
      }
      if (j < 3)
        stageB_async(g_w1 + (l * 4 + j + 1) * 4096, (j & 1) ? a_B : a_v, tid);
      CP_WAIT_ALL;
      __syncthreads();
      gemm_core(a_aM, a_w2, w, lane, acc);
      {
        const float* bp = (j == 3) ? (b2 + l * 64) : nullptr;
#pragma unroll
        for (int nt = 0; nt < 8; nt++) {
          int col = nt * 8 + tg * 2;
          float bv0 = bp ? __ldg(bp + col) : 0.f;
          float bv1 = bp ? __ldg(bp + col + 1) : 0.f;
          float2* x0 = (float2*)(xs + r0 * 68 + col);
          float2* x1 = (float2*)(xs + (r0 + 8) * 68 + col);
          float2 v0 = *x0, v1 = *x1;
          v0.x += acc[nt][0] + bv0; v0.y += acc[nt][1] + bv1;
          v1.x += acc[nt][2] + bv0; v1.y += acc[nt][3] + bv1;
          *x0 = v0; *x1 = v1;
        }
      }
      if (j < 3)
        stageB_async(g_w2 + (l * 4 + j + 1) * 4096,
                     a_k + ((j & 1) ? 0 : 8192), tid);
      CP_WAIT_ALL;
      __syncthreads();
    }
  }

  // ---- final LN -> split fp16 operands Ah @ O_AA, Al @ O_Q ----
  stageB96_async(g_lmh, a_k, tid);
  stageB96_async(g_lml, a_k + 12288, tid);
  if (tid < 128) {
    float v[64];
    ln_row(xs + tid * 68, v, lnf_g, lnf_b);
    char* Alc = sm + O_Q;
#pragma unroll
    for (int q8 = 0; q8 < 8; q8++) {
      uint32_t hh[4], hl[4];
#pragma unroll
      for (int e = 0; e < 4; e++) {
        float v0 = v[q8 * 8 + e * 2], v1 = v[q8 * 8 + e * 2 + 1];
        hh[e] = f2h2(v0, v1);
        __half2 hi2 = *(__half2*)&hh[e];
        float2 hif = __half22float2(hi2);
        hl[e] = f2h2(v0 - hif.x, v1 - hif.y);
      }
      *(uint4*)(aAc + SW(tid, q8 * 16)) = *(uint4*)hh;
      *(uint4*)(Alc + SW(tid, q8 * 16)) = *(uint4*)hl;
    }
  }
  CP_WAIT_ALL;
  __syncthreads();

  // ---- LM head: 128x96x64 split GEMM on tensor cores ----
  float lacc[12][4];
#pragma unroll
  for (int nt = 0; nt < 12; nt++)
#pragma unroll
    for (int e = 0; e < 4; e++) lacc[nt][e] = 0.f;
  lm_pass(a_aA, a_k, w, lane, lacc);          // Ah @ Bh
  lm_pass(a_q, a_k, w, lane, lacc);           // Al @ Bh
  lm_pass(a_aA, a_k + 12288, w, lane, lacc);  // Ah @ Bl
  __syncthreads();

  float* sl = (float*)(sm + O_Q);
  {
#pragma unroll
    for (int nt = 0; nt < 12; nt++) {
      int col = nt * 8 + tg * 2;
      float bv0 = __ldg(lm_b + col), bv1 = __ldg(lm_b + col + 1);
      float2 o0 = make_float2(lacc[nt][0] + bv0, lacc[nt][1] + bv1);
      float2 o1 = make_float2(lacc[nt][2] + bv0, lacc[nt][3] + bv1);
      *(float2*)(sl + r0 * 96 + col) = o0;
      *(float2*)(sl + (r0 + 8) * 96 + col) = o1;
      if (write_logits) {
        float* ob = out + (size_t)(b * 128 + r0) * 96 + col;
        *(float2*)ob = o0;
        *(float2*)(ob + 8 * 96) = o1;
      }
    }
  }
  __syncthreads();

  // ---- loss ----
  {
    int r = tid >> 1, p = tid & 1;
    const float* row = sl + r * 96 + p * 48;
    float m = -1e30f;
#pragma unroll
    for (int j = 0; j < 48; j++) m = fmaxf(m, row[j]);
    m = fmaxf(m, __shfl_xor_sync(0xffffffffu, m, 1));
    float se = 0.f;
#pragma unroll
    for (int j = 0; j < 48; j++) se += __expf(row[j] - m);
    se += __shfl_xor_sync(0xffffffffu, se, 1);
    float lse = m + logf(se);
    int tgt = targets[b * 128 + r];
    float contrib = 0.f;
    int rel = tgt - p * 48;
    if (rel >= 0 && rel < 48) contrib = row[rel] - lse;
    contrib += __shfl_xor_sync(0xffffffffu, contrib, 1);
    if (p == 0) sred[r] = contrib;
  }
  __syncthreads();
  if (tid < 128) {
    float v = sred[tid];
#pragma unroll
    for (int o = 16; o; o >>= 1) v += __shfl_xor_sync(0xffffffffu, v, o);
    if ((tid & 31) == 0) sred[128 + (tid >> 5)] = v;
  }
  __syncthreads();
  if (tid == 0)
    g_partial[b] = sred[128] + sred[129] + sred[130] + sred[131];
}

__global__ void loss_reduce_kernel(float* __restrict__ dst) {
  __shared__ float sh[8];
  float v = 0.f;
  for (int i = threadIdx.x; i < NCTAS; i += NTHREADS) v += g_partial[i];
#pragma unroll
  for (int o = 16; o; o >>= 1) v += __shfl_xor_sync(0xffffffffu, v, o);
  if ((threadIdx.x & 31) == 0) sh[threadIdx.x >> 5] = v;
  __syncthreads();
  if (threadIdx.x == 0) {
    float s = 0.f;
    for (int w = 0; w < 8; w++) s += sh[w];
    dst[0] = -s / (float)(4096 * 64);
  }
}

extern "C" void kernel_launch(void* const* d_in, const int* in_sizes, int n_in,
                              void* d_out, int out_size) {
  const int* idx = (const int*)d_in[0];
  const int* targets = (const int*)d_in[1];
  const float* tok_emb = (const float*)d_in[2];
  const float* pos_emb = (const float*)d_in[3];
  const float* ln1_g = (const float*)d_in[4];
  const float* ln1_b = (const float*)d_in[5];
  const float* wq = (const float*)d_in[6];
  const float* wk = (const float*)d_in[7];
  const float* wv = (const float*)d_in[8];
  const float* wo = (const float*)d_in[9];
  const float* bo = (const float*)d_in[10];
  const float* ln2_g = (const float*)d_in[11];
  const float* ln2_b = (const float*)d_in[12];
  const float* w1 = (const float*)d_in[13];
  const float* b1 = (const float*)d_in[14];
  const float* w2 = (const float*)d_in[15];
  const float* b2 = (const float*)d_in[16];
  const float* lnf_g = (const float*)d_in[17];
  const float* lnf_b = (const float*)d_in[18];
  const float* lm_w = (const float*)d_in[19];
  const float* lm_b = (const float*)d_in[20];
  float* out = (float*)d_out;

  cudaFuncSetAttribute(slm_kernel, cudaFuncAttributeMaxDynamicSharedMemorySize,
                       SMEM_BYTES);

  prep_kernel<<<792, 256>>>(wq, wk, wv, wo, w1, w2, lm_w);

  int write_logits = (out_size >= BTV) ? 1 : 0;
  slm_kernel<<<NCTAS, NTHREADS, SMEM_BYTES>>>(
      idx, targets, tok_emb, pos_emb, ln1_g, ln1_b, bo, ln2_g, ln2_b, b1, b2,
      lnf_g, lnf_b, lm_b, out, write_logits);

  if (out_size > BTV)
    loss_reduce_kernel<<<1, NTHREADS>>>(out + BTV);
  else if (out_size < BTV)
    loss_reduce_kernel<<<1, NTHREADS>>>(out);
}

// round 17
// speedup vs baseline: 1.6326x; 1.0165x over previous
#include <cuda_runtime.h>
#include <cuda_fp16.h>
#include <stdint.h>
#include <math.h>

#define NTHREADS 256
#define NCTAS 2048
#define BTV (4096 * 64 * 96)

#define O_XS 0
#define O_AA 34816
#define O_B 51200
#define O_Q 59392
#define O_K 75776
#define O_V 92160
#define O_SRED 108544
#define SMEM_BYTES 110592

#define SW(r, inner) ((r) * 128 + ((inner) ^ (((r) & 7) << 4)))

__device__ __align__(16) __half g_wqkv[49152];
__device__ __align__(16) __half g_wo[16384];
__device__ __align__(16) __half g_w1[65536];
__device__ __align__(16) __half g_w2[65536];
__device__ __align__(16) __half g_lmh[6144];
__device__ __align__(16) __half g_lml[6144];
__device__ float g_partial[NCTAS];

__device__ __forceinline__ uint32_t smem_u32(const void* p) {
  uint32_t a;
  asm("{ .reg .u64 t; cvta.to.shared.u64 t, %1; cvt.u32.u64 %0, t; }"
      : "=r"(a) : "l"(p));
  return a;
}
__device__ __forceinline__ uint32_t f2h2(float x, float y) {
  __half2 h = __floats2half2_rn(x, y);
  return *(uint32_t*)&h;
}

#define CP_WAIT_ALL asm volatile("cp.async.wait_all;" ::: "memory")

__device__ __forceinline__ void stageB_async(const __half* __restrict__ g,
                                             uint32_t s, int tid) {
  const char* src = (const char*)g;
  for (int i = tid; i < 512; i += NTHREADS) {
    int n = i >> 3, u = (i & 7) * 16;
    asm volatile("cp.async.ca.shared.global [%0], [%1], 16;" ::
                     "r"(s + SW(n, u)),
                 "l"(src + i * 16) : "memory");
  }
}
__device__ __forceinline__ void stageB96_async(const __half* __restrict__ g,
                                               uint32_t s, int tid) {
  const char* src = (const char*)g;
  for (int i = tid; i < 768; i += NTHREADS) {
    int n = i >> 3, u = (i & 7) * 16;
    asm volatile("cp.async.ca.shared.global [%0], [%1], 16;" ::
                     "r"(s + SW(n, u)),
                 "l"(src + i * 16) : "memory");
  }
}

#define LDSM_X4(a0, a1, a2, a3, addr)                                        \
  asm volatile("ldmatrix.sync.aligned.m8n8.x4.shared.b16 {%0,%1,%2,%3}, [%4];" \
               : "=r"(a0), "=r"(a1), "=r"(a2), "=r"(a3) : "r"(addr))
#define LDSM_X2(b0, b1, addr)                                                \
  asm volatile("ldmatrix.sync.aligned.m8n8.x2.shared.b16 {%0,%1}, [%2];"     \
               : "=r"(b0), "=r"(b1) : "r"(addr))
#define LDSM_X4T(a0, a1, a2, a3, addr)                                       \
  asm volatile(                                                              \
      "ldmatrix.sync.aligned.m8n8.x4.trans.shared.b16 {%0,%1,%2,%3}, [%4];"  \
      : "=r"(a0), "=r"(a1), "=r"(a2), "=r"(a3) : "r"(addr))
#define MMA16816(c, a0, a1, a2, a3, b0, b1)                                  \
  asm volatile(                                                              \
      "mma.sync.aligned.m16n8k16.row.col.f32.f16.f16.f32 "                   \
      "{%0,%1,%2,%3}, {%4,%5,%6,%7}, {%8,%9}, {%0,%1,%2,%3};"                \
      : "+f"((c)[0]), "+f"((c)[1]), "+f"((c)[2]), "+f"((c)[3])               \
      : "r"(a0), "r"(a1), "r"(a2), "r"(a3), "r"(b0), "r"(b1))

// 128x64x64 GEMM (x2 B loads — proven fastest form)
__device__ __forceinline__ void gemm_core(uint32_t a_addr, uint32_t b_addr,
                                          int w, int lane, float acc[8][4]) {
#pragma unroll
  for (int nt = 0; nt < 8; nt++)
#pragma unroll
    for (int e = 0; e < 4; e++) acc[nt][e] = 0.f;
  const int l15 = lane & 15;
  const int ahi = (lane >> 4) << 4;
  const int rowA = w * 16 + l15;
  const uint32_t a_base = a_addr + rowA * 128;
  const int aswz = (rowA & 7) << 4;
  const int bl = lane & 7;
  const int bhi = (lane & 8) << 1;
#pragma unroll
  for (int kt = 0; kt < 4; kt++) {
    uint32_t a0, a1, a2, a3;
    LDSM_X4(a0, a1, a2, a3, a_base + ((kt * 32 + ahi) ^ aswz));
#pragma unroll
    for (int nt = 0; nt < 8; nt++) {
      uint32_t b0, b1;
      LDSM_X2(b0, b1, b_addr + SW(nt * 8 + bl, kt * 32 + bhi));
      MMA16816(acc[nt], a0, a1, a2, a3, b0, b1);
    }
  }
}

// 128x96x64 accumulate pass (LM head)
__device__ __forceinline__ void lm_pass(uint32_t a_addr, uint32_t b_addr,
                                        int w, int lane, float acc[12][4]) {
  const int l15 = lane & 15;
  const int ahi = (lane >> 4) << 4;
  const int rowA = w * 16 + l15;
  const uint32_t a_base = a_addr + rowA * 128;
  const int aswz = (rowA & 7) << 4;
  const int bl = lane & 7;
  const int bhi = (lane & 8) << 1;
#pragma unroll
  for (int kt = 0; kt < 4; kt++) {
    uint32_t a0, a1, a2, a3;
    LDSM_X4(a0, a1, a2, a3, a_base + ((kt * 32 + ahi) ^ aswz));
#pragma unroll
    for (int nt = 0; nt < 12; nt++) {
      uint32_t b0, b1;
      LDSM_X2(b0, b1, b_addr + SW(nt * 8 + bl, kt * 32 + bhi));
      MMA16816(acc[nt], a0, a1, a2, a3, b0, b1);
    }
  }
}

// LayerNorm of xs row -> v[64] (128 threads, proven form)
__device__ __forceinline__ void ln_row(const float* row, float* v,
                                       const float* __restrict__ g,
                                       const float* __restrict__ b) {
  float s = 0.f, ss = 0.f;
#pragma unroll
  for (int i = 0; i < 16; i++) {
    float4 a = *(const float4*)(row + i * 4);
    v[i * 4] = a.x; v[i * 4 + 1] = a.y; v[i * 4 + 2] = a.z; v[i * 4 + 3] = a.w;
    s += a.x + a.y + a.z + a.w;
    ss += a.x * a.x + a.y * a.y + a.z * a.z + a.w * a.w;
  }
  float mean = s * 0.015625f;
  float inv = rsqrtf(ss * 0.015625f - mean * mean + 1e-5f);
#pragma unroll
  for (int c = 0; c < 64; c++)
    v[c] = (v[c] - mean) * inv * __ldg(g + c) + __ldg(b + c);
}

__device__ __forceinline__ void row_to_A(const float* v, char* aAc, int r) {
#pragma unroll
  for (int q8 = 0; q8 < 8; q8++) {
    uint32_t h[4];
#pragma unroll
    for (int e = 0; e < 4; e++)
      h[e] = f2h2(v[q8 * 8 + e * 2], v[q8 * 8 + e * 2 + 1]);
    *(uint4*)(aAc + SW(r, q8 * 16)) = *(uint4*)h;
  }
}

// ---------------- prep ----------------------------------------------------
__global__ void prep_kernel(const float* __restrict__ wq,
                            const float* __restrict__ wk,
                            const float* __restrict__ wv,
                            const float* __restrict__ wo,
                            const float* __restrict__ w1,
                            const float* __restrict__ w2,
                            const float* __restrict__ lm_w) {
  int i = blockIdx.x * blockDim.x + threadIdx.x;
  if (i < 49152) {
    int l = i / 12288, rr = i % 12288;
    int m = rr / 4096, r2 = rr % 4096;
    int n = r2 >> 6, k = r2 & 63;
    int h = n >> 4, s = n & 15;
    const float* src = (m == 0) ? wq : (m == 1) ? wk : wv;
    g_wqkv[i] = __float2half(src[l * 4096 + h * 1024 + k * 16 + s]);
  } else if (i < 65536) {
    int j = i - 49152;
    int l = j >> 12, n = (j >> 6) & 63, k = j & 63;
    g_wo[j] = __float2half(wo[l * 4096 + k * 64 + n]);
  } else if (i < 131072) {
    int j = i - 65536;
    int lj = j >> 12, n = (j >> 6) & 63, k = j & 63;
    int l = lj >> 2, jj = lj & 3;
    g_w1[j] = __float2half(w1[l * 16384 + k * 256 + jj * 64 + n]);
  } else if (i < 196608) {
    int j = i - 131072;
    int lj = j >> 12, n = (j >> 6) & 63, k = j & 63;
    int l = lj >> 2, jj = lj & 3;
    g_w2[j] = __float2half(w2[l * 16384 + (jj * 64 + k) * 64 + n]);
  } else if (i < 202752) {
    int j = i - 196608;
    int n = j >> 6, k = j & 63;
    float v = lm_w[k * 96 + n];
    __half hi = __float2half(v);
    g_lmh[j] = hi;
    g_lml[j] = __float2half(v - __half2float(hi));
  }
}

// ---------------- main fused kernel: 1 CTA = 2 sequences ------------------
__global__ void __launch_bounds__(NTHREADS, 2) slm_kernel(
    const int* __restrict__ idx, const int* __restrict__ targets,
    const float* __restrict__ tok_emb, const float* __restrict__ pos_emb,
    const float* __restrict__ ln1_g, const float* __restrict__ ln1_b,
    const float* __restrict__ bo, const float* __restrict__ ln2_g,
    const float* __restrict__ ln2_b, const float* __restrict__ b1,
    const float* __restrict__ b2, const float* __restrict__ lnf_g,
    const float* __restrict__ lnf_b, const float* __restrict__ lm_b,
    float* __restrict__ out, int write_logits) {
  extern __shared__ char sm[];
  float* xs = (float*)(sm + O_XS);
  char* aAc = sm + O_AA;
  float* sred = (float*)(sm + O_SRED);
  const int b = blockIdx.x;
  const int tid = threadIdx.x;
  const int w = tid >> 5, lane = tid & 31;
  const int g = lane >> 2, tg = lane & 3;
  const int r0 = w * 16 + g;
  const uint32_t smb = smem_u32(sm);
  const uint32_t a_aA = smb + O_AA, a_B = smb + O_B;
  const uint32_t a_q = smb + O_Q, a_k = smb + O_K, a_v = smb + O_V;

  // embedding: float4 vectorized
  for (int i = tid; i < 2048; i += NTHREADS) {
    int r = i >> 4, c4 = (i & 15) * 4;
    float4 t = *(const float4*)(tok_emb + idx[b * 128 + r] * 64 + c4);
    float4 p = *(const float4*)(pos_emb + (r & 63) * 64 + c4);
    t.x += p.x; t.y += p.y; t.z += p.z; t.w += p.w;
    *(float4*)(xs + r * 68 + c4) = t;
  }
  __syncthreads();

  float acc[8][4];

  for (int l = 0; l < 4; l++) {
    // ---- ln1 -> A; prestage wq->B, wk->O_V(temp) (async) ----
    stageB_async(g_wqkv + (l * 3 + 0) * 4096, a_B, tid);
    stageB_async(g_wqkv + (l * 3 + 1) * 4096, a_v, tid);
    if (tid < 128) {
      float v[64];
      ln_row(xs + tid * 68, v, ln1_g + l * 64, ln1_b + l * 64);
      row_to_A(v, aAc, tid);
    }
    CP_WAIT_ALL;
    __syncthreads();
    // ---- Q GEMM (B=wq) ----
    gemm_core(a_aA, a_B, w, lane, acc);
#pragma unroll
    for (int nt = 0; nt < 8; nt++) {
      int col = nt * 8 + tg * 2;
      *(uint32_t*)(sm + O_Q + SW(r0, col * 2)) = f2h2(acc[nt][0], acc[nt][1]);
      *(uint32_t*)(sm + O_Q + SW(r0 + 8, col * 2)) =
          f2h2(acc[nt][2], acc[nt][3]);
    }
    __syncthreads();
    // ---- K GEMM (B=wk in O_V temp); stage wv->B meanwhile ----
    stageB_async(g_wqkv + (l * 3 + 2) * 4096, a_B, tid);
    gemm_core(a_aA, a_v, w, lane, acc);
#pragma unroll
    for (int nt = 0; nt < 8; nt++) {
      int col = nt * 8 + tg * 2;
      *(uint32_t*)(sm + O_K + SW(r0, col * 2)) = f2h2(acc[nt][0], acc[nt][1]);
      *(uint32_t*)(sm + O_K + SW(r0 + 8, col * 2)) =
          f2h2(acc[nt][2], acc[nt][3]);
    }
    CP_WAIT_ALL;
    __syncthreads();
    // ---- V GEMM (B=wv), overwrites wk temp in O_V ----
    gemm_core(a_aA, a_B, w, lane, acc);
#pragma unroll
    for (int nt = 0; nt < 8; nt++) {
      int col = nt * 8 + tg * 2;
      *(uint32_t*)(sm + O_V + SW(r0, col * 2)) = f2h2(acc[nt][0], acc[nt][1]);
      *(uint32_t*)(sm + O_V + SW(r0 + 8, col * 2)) =
          f2h2(acc[nt][2], acc[nt][3]);
    }
    __syncthreads();
    // ---- attention: warp = (seq, head); balanced causal skip ----
    stageB_async(g_wo + l * 4096, a_B, tid);
    {
      const int bl = lane & 7;
      const int l15 = lane & 15;
      const int ahi = (lane >> 4) << 4;
      const int bhi = (lane & 8) << 1;
      const int vgrp = lane >> 4;
      const int seq0a = (w >> 2) * 64;
      const int h = w & 3;
      const int hb = h * 32;
#pragma unroll
      for (int mi = 0; mi < 4; mi++) {
        const int rowA = seq0a + mi * 16 + l15;
        uint32_t a0, a1, a2, a3;
        LDSM_X4(a0, a1, a2, a3,
                a_q + rowA * 128 + ((hb + ahi) ^ ((rowA & 7) << 4)));
        const int NT = 2 * (mi + 1);
        float S[8][4];
#pragma unroll
        for (int nt = 0; nt < 8; nt++) {
          if (nt >= NT) break;
#pragma unroll
          for (int e = 0; e < 4; e++) S[nt][e] = 0.f;
          uint32_t b0, b1;
          LDSM_X2(b0, b1, a_k + SW(seq0a + nt * 8 + bl, hb + bhi));
          MMA16816(S[nt], a0, a1, a2, a3, b0, b1);
        }
        const int tlo = mi * 16 + g;
        float mx0 = -1e30f, mx1 = -1e30f;
#pragma unroll
        for (int nt = 0; nt < 8; nt++) {
          if (nt >= NT) break;
          int c0 = nt * 8 + tg * 2;
          S[nt][0] = (c0 <= tlo) ? S[nt][0] * 0.25f : -1e30f;
          S[nt][1] = (c0 + 1 <= tlo) ? S[nt][1] * 0.25f : -1e30f;
          S[nt][2] = (c0 <= tlo + 8) ? S[nt][2] * 0.25f : -1e30f;
          S[nt][3] = (c0 + 1 <= tlo + 8) ? S[nt][3] * 0.25f : -1e30f;
          mx0 = fmaxf(mx0, fmaxf(S[nt][0], S[nt][1]));
          mx1 = fmaxf(mx1, fmaxf(S[nt][2], S[nt][3]));
        }
        mx0 = fmaxf(mx0, __shfl_xor_sync(0xffffffffu, mx0, 1));
        mx0 = fmaxf(mx0, __shfl_xor_sync(0xffffffffu, mx0, 2));
        mx1 = fmaxf(mx1, __shfl_xor_sync(0xffffffffu, mx1, 1));
        mx1 = fmaxf(mx1, __shfl_xor_sync(0xffffffffu, mx1, 2));
        float sum0 = 0.f, sum1 = 0.f;
#pragma unroll
        for (int nt = 0; nt < 8; nt++) {
          if (nt >= NT) break;
          S[nt][0] = __expf(S[nt][0] - mx0);
          S[nt][1] = __expf(S[nt][1] - mx0);
          S[nt][2] = __expf(S[nt][2] - mx1);
          S[nt][3] = __expf(S[nt][3] - mx1);
          sum0 += S[nt][0] + S[nt][1];
          sum1 += S[nt][2] + S[nt][3];
        }
        sum0 += __shfl_xor_sync(0xffffffffu, sum0, 1);
        sum0 += __shfl_xor_sync(0xffffffffu, sum0, 2);
        sum1 += __shfl_xor_sync(0xffffffffu, sum1, 1);
        sum1 += __shfl_xor_sync(0xffffffffu, sum1, 2);
        float ri0 = 1.f / sum0, ri1 = 1.f / sum1;
        float O[2][4];
#pragma unroll
        for (int nt = 0; nt < 2; nt++)
#pragma unroll
          for (int e = 0; e < 4; e++) O[nt][e] = 0.f;
#pragma unroll
        for (int kb = 0; kb < 4; kb++) {
          if (kb > mi) break;
          uint32_t p0 = f2h2(S[2 * kb][0] * ri0, S[2 * kb][1] * ri0);
          uint32_t p1 = f2h2(S[2 * kb][2] * ri1, S[2 * kb][3] * ri1);
          uint32_t p2 = f2h2(S[2 * kb + 1][0] * ri0, S[2 * kb + 1][1] * ri0);
          uint32_t p3 = f2h2(S[2 * kb + 1][2] * ri1, S[2 * kb + 1][3] * ri1);
          int ur = seq0a + kb * 16 + bl + ((lane & 8) ? 8 : 0);
          uint32_t b0, b1, b2, b3;
          LDSM_X4T(b0, b1, b2, b3, a_v + SW(ur, hb + vgrp * 16));
          MMA16816(O[0], p0, p1, p2, p3, b0, b1);
          MMA16816(O[1], p0, p1, p2, p3, b2, b3);
        }
        const int orow = seq0a + mi * 16 + g;
#pragma unroll
        for (int nt = 0; nt < 2; nt++) {
          int col = h * 16 + nt * 8 + tg * 2;
          *(uint32_t*)(aAc + SW(orow, col * 2)) = f2h2(O[nt][0], O[nt][1]);
          *(uint32_t*)(aAc + SW(orow + 8, col * 2)) = f2h2(O[nt][2], O[nt][3]);
        }
      }
    }
    CP_WAIT_ALL;
    __syncthreads();
    // ---- WO GEMM (wo prestaged): xs += d + bo (float2 epilogue) ----
    gemm_core(a_aA, a_B, w, lane, acc);
    {
      const float* bp = bo + l * 64;
#pragma unroll
      for (int nt = 0; nt < 8; nt++) {
        int col = nt * 8 + tg * 2;
        float2 bv = __ldg((const float2*)(bp + col));
        float2* x0 = (float2*)(xs + r0 * 68 + col);
        float2* x1 = (float2*)(xs + (r0 + 8) * 68 + col);
        float2 v0 = *x0, v1 = *x1;
        v0.x += acc[nt][0] + bv.x; v0.y += acc[nt][1] + bv.y;
        v1.x += acc[nt][2] + bv.x; v1.y += acc[nt][3] + bv.y;
        *x0 = v0; *x1 = v1;
      }
    }
    __syncthreads();
    // ---- ln2 -> A; prestage first MLP chunk (async) ----
    stageB_async(g_w1 + (l * 4) * 4096, a_B, tid);
    stageB_async(g_w2 + (l * 4) * 4096, a_k, tid);
    if (tid < 128) {
      float v[64];
      ln_row(xs + tid * 68, v, ln2_g + l * 64, ln2_b + l * 64);
      row_to_A(v, aAc, tid);
    }
    CP_WAIT_ALL;
    __syncthreads();
    // ---- MLP: double-buffered w1 (B / O_V), w2 (O_K halves) ----
    char* aMc = sm + O_Q;
    const uint32_t a_aM = a_q;
    for (int j = 0; j < 4; j++) {
      uint32_t a_w1 = (j & 1) ? a_v : a_B;
      uint32_t a_w2 = a_k + ((j & 1) ? 8192 : 0);
      gemm_core(a_aA, a_w1, w, lane, acc);
      {
        const float* bp = b1 + l * 256 + j * 64;
#pragma unroll
        for (int nt = 0; nt < 8; nt++) {
          int col = nt * 8 + tg * 2;
          float2 bv = __ldg((const float2*)(bp + col));
          *(uint32_t*)(aMc + SW(r0, col * 2)) = f2h2(
              fmaxf(acc[nt][0] + bv.x, 0.f), fmaxf(acc[nt][1] + bv.y, 0.f));
          *(uint32_t*)(aMc + SW(r0 + 8, col * 2)) = f2h2(
              fmaxf(acc[nt][2] + bv.x, 0.f), fmaxf(acc[nt][3] + bv.y, 0.f));
        }
      }
      if (j < 3)
        stageB_async(g_w1 + (l * 4 + j + 1) * 4096, (j & 1) ? a_B : a_v, tid);
      CP_WAIT_ALL;
      __syncthreads();
      gemm_core(a_aM, a_w2, w, lane, acc);
      {
        const float* bp = (j == 3) ? (b2 + l * 64) : nullptr;
#pragma unroll
        for (int nt = 0; nt < 8; nt++) {
          int col = nt * 8 + tg * 2;
          float2 bv = make_float2(0.f, 0.f);
          if (bp) bv = __ldg((const float2*)(bp + col));
          float2* x0 = (float2*)(xs + r0 * 68 + col);
          float2* x1 = (float2*)(xs + (r0 + 8) * 68 + col);
          float2 v0 = *x0, v1 = *x1;
          v0.x += acc[nt][0] + bv.x; v0.y += acc[nt][1] + bv.y;
          v1.x += acc[nt][2] + bv.x; v1.y += acc[nt][3] + bv.y;
          *x0 = v0; *x1 = v1;
        }
      }
      if (j < 3)
        stageB_async(g_w2 + (l * 4 + j + 1) * 4096,
                     a_k + ((j & 1) ? 0 : 8192), tid);
      CP_WAIT_ALL;
      __syncthreads();
    }
  }

  // ---- final LN -> split fp16 operands Ah @ O_AA, Al @ O_Q ----
  stageB96_async(g_lmh, a_k, tid);
  stageB96_async(g_lml, a_k + 12288, tid);
  if (tid < 128) {
    float v[64];
    ln_row(xs + tid * 68, v, lnf_g, lnf_b);
    char* Alc = sm + O_Q;
#pragma unroll
    for (int q8 = 0; q8 < 8; q8++) {
      uint32_t hh[4], hl[4];
#pragma unroll
      for (int e = 0; e < 4; e++) {
        float v0 = v[q8 * 8 + e * 2], v1 = v[q8 * 8 + e * 2 + 1];
        hh[e] = f2h2(v0, v1);
        __half2 hi2 = *(__half2*)&hh[e];
        float2 hif = __half22float2(hi2);
        hl[e] = f2h2(v0 - hif.x, v1 - hif.y);
      }
      *(uint4*)(aAc + SW(tid, q8 * 16)) = *(uint4*)hh;
      *(uint4*)(Alc + SW(tid, q8 * 16)) = *(uint4*)hl;
    }
  }
  CP_WAIT_ALL;
  __syncthreads();

  // ---- LM head: 128x96x64 split GEMM on tensor cores ----
  float lacc[12][4];
#pragma unroll
  for (int nt = 0; nt < 12; nt++)
#pragma unroll
    for (int e = 0; e < 4; e++) lacc[nt][e] = 0.f;
  lm_pass(a_aA, a_k, w, lane, lacc);          // Ah @ Bh
  lm_pass(a_q, a_k, w, lane, lacc);           // Al @ Bh
  lm_pass(a_aA, a_k + 12288, w, lane, lacc);  // Ah @ Bl
  __syncthreads();

  float* sl = (float*)(sm + O_Q);
  {
#pragma unroll
    for (int nt = 0; nt < 12; nt++) {
      int col = nt * 8 + tg * 2;
      float2 bv = __ldg((const float2*)(lm_b + col));
      float2 o0 = make_float2(lacc[nt][0] + bv.x, lacc[nt][1] + bv.y);
      float2 o1 = make_float2(lacc[nt][2] + bv.x, lacc[nt][3] + bv.y);
      *(float2*)(sl + r0 * 96 + col) = o0;
      *(float2*)(sl + (r0 + 8) * 96 + col) = o1;
      if (write_logits) {
        float* ob = out + (size_t)(b * 128 + r0) * 96 + col;
        *(float2*)ob = o0;
        *(float2*)(ob + 8 * 96) = o1;
      }
    }
  }
  __syncthreads();

  // ---- loss: float4 row reads ----
  {
    int r = tid >> 1, p = tid & 1;
    const float4* row4 = (const float4*)(sl + r * 96 + p * 48);
    float m = -1e30f;
#pragma unroll
    for (int j = 0; j < 12; j++) {
      float4 v = row4[j];
      m = fmaxf(m, fmaxf(fmaxf(v.x, v.y), fmaxf(v.z, v.w)));
    }
    m = fmaxf(m, __shfl_xor_sync(0xffffffffu, m, 1));
    float se = 0.f;
#pragma unroll
    for (int j = 0; j < 12; j++) {
      float4 v = row4[j];
      se += __expf(v.x - m);
      se += __expf(v.y - m);
      se += __expf(v.z - m);
      se += __expf(v.w - m);
    }
    se += __shfl_xor_sync(0xffffffffu, se, 1);
    float lse = m + logf(se);
    int tgt = targets[b * 128 + r];
    float contrib = 0.f;
    int rel = tgt - p * 48;
    if (rel >= 0 && rel < 48) contrib = ((const float*)row4)[rel] - lse;
    contrib += __shfl_xor_sync(0xffffffffu, contrib, 1);
    if (p == 0) sred[r] = contrib;
  }
  __syncthreads();
  if (tid < 128) {
    float v = sred[tid];
#pragma unroll
    for (int o = 16; o; o >>= 1) v += __shfl_xor_sync(0xffffffffu, v, o);
    if ((tid & 31) == 0) sred[128 + (tid >> 5)] = v;
  }
  __syncthreads();
  if (tid == 0)
    g_partial[b] = sred[128] + sred[129] + sred[130] + sred[131];
}

__global__ void loss_reduce_kernel(float* __restrict__ dst) {
  __shared__ float sh[8];
  float v = 0.f;
  for (int i = threadIdx.x; i < NCTAS; i += NTHREADS) v += g_partial[i];
#pragma unroll
  for (int o = 16; o; o >>= 1) v += __shfl_xor_sync(0xffffffffu, v, o);
  if ((threadIdx.x & 31) == 0) sh[threadIdx.x >> 5] = v;
  __syncthreads();
  if (threadIdx.x == 0) {
    float s = 0.f;
    for (int w = 0; w < 8; w++) s += sh[w];
    dst[0] = -s / (float)(4096 * 64);
  }
}

extern "C" void kernel_launch(void* const* d_in, const int* in_sizes, int n_in,
                              void* d_out, int out_size) {
  const int* idx = (const int*)d_in[0];
  const int* targets = (const int*)d_in[1];
  const float* tok_emb = (const float*)d_in[2];
  const float* pos_emb = (const float*)d_in[3];
  const float* ln1_g = (const float*)d_in[4];
  const float* ln1_b = (const float*)d_in[5];
  const float* wq = (const float*)d_in[6];
  const float* wk = (const float*)d_in[7];
  const float* wv = (const float*)d_in[8];
  const float* wo = (const float*)d_in[9];
  const float* bo = (const float*)d_in[10];
  const float* ln2_g = (const float*)d_in[11];
  const float* ln2_b = (const float*)d_in[12];
  const float* w1 = (const float*)d_in[13];
  const float* b1 = (const float*)d_in[14];
  const float* w2 = (const float*)d_in[15];
  const float* b2 = (const float*)d_in[16];
  const float* lnf_g = (const float*)d_in[17];
  const float* lnf_b = (const float*)d_in[18];
  const float* lm_w = (const float*)d_in[19];
  const float* lm_b = (const float*)d_in[20];
  float* out = (float*)d_out;

  cudaFuncSetAttribute(slm_kernel, cudaFuncAttributeMaxDynamicSharedMemorySize,
                       SMEM_BYTES);

  prep_kernel<<<792, 256>>>(wq, wk, wv, wo, w1, w2, lm_w);

  int write_logits = (out_size >= BTV) ? 1 : 0;
  slm_kernel<<<NCTAS, NTHREADS, SMEM_BYTES>>>(
      idx, targets, tok_emb, pos_emb, ln1_g, ln1_b, bo, ln2_g, ln2_b, b1, b2,
      lnf_g, lnf_b, lm_b, out, write_logits);

  if (out_size > BTV)
    loss_reduce_kernel<<<1, NTHREADS>>>(out + BTV);
  else if (out_size < BTV)
    loss_reduce_kernel<<<1, NTHREADS>>>(out);
}